// round 10
// baseline (speedup 1.0000x reference)
#include <cuda_runtime.h>
#include <cuda_bf16.h>
#include <cstdint>

#define CIN 128
#define C 64
#define H2f 0.01f
#define NNODES 50000
#define NEDGES 800000
#define TE 128
#define GSB 72          // smem tile row stride in bf16 (144B)

#define GT_BYTES (TE * GSB * 2)
#define BS_BYTES (C * GSB * 2)
#define SMEM_EDGE (3 * GT_BYTES + BS_BYTES + 4 * TE * 12)

__device__ float g_deg[NNODES];
__device__ float g_W[NEDGES];
__device__ float g_buf[3][(long)NNODES * C];
__device__ uint32_t g_xbf[(long)NNODES * C / 2];   // bf16 mirror of x_cur

// ---------------- helpers ----------------
__device__ __forceinline__ uint32_t smem_u32(const void* p) {
    uint32_t a;
    asm("{ .reg .u64 t; cvta.to.shared.u64 t, %1; cvt.u32.u64 %0, t; }"
        : "=r"(a) : "l"(p));
    return a;
}
__device__ __forceinline__ float tanh_fast(float x) {
    float y;
    asm("tanh.approx.f32 %0, %1;" : "=f"(y) : "f"(x));
    return y;
}
// pack bf16x2: lo = a, hi = b
__device__ __forceinline__ uint32_t bf16x2_pack(float a, float b) {
    uint32_t r;
    asm("cvt.rn.satfinite.bf16x2.f32 %0, %1, %2;" : "=r"(r) : "f"(b), "f"(a));
    return r;
}
// g = w2 * (xi - xj), all bf16x2 packed in u32
__device__ __forceinline__ uint32_t gdiff(uint32_t xi, uint32_t xj, uint32_t w2) {
    __nv_bfloat162 a = *(__nv_bfloat162*)&xi;
    __nv_bfloat162 b = *(__nv_bfloat162*)&xj;
    __nv_bfloat162 w = *(__nv_bfloat162*)&w2;
    __nv_bfloat162 r = __hmul2(w, __hsub2(a, b));
    return *(uint32_t*)&r;
}
__device__ __forceinline__ void ldsm4(uint32_t (&r)[4], uint32_t addr) {
    asm volatile("ldmatrix.sync.aligned.m8n8.x4.shared.b16 {%0,%1,%2,%3}, [%4];"
        : "=r"(r[0]), "=r"(r[1]), "=r"(r[2]), "=r"(r[3]) : "r"(addr));
}
__device__ __forceinline__ void mma_bf16(float (&d)[4], const uint32_t (&a)[4],
                                         uint32_t b0, uint32_t b1) {
    asm volatile("mma.sync.aligned.m16n8k16.row.col.f32.bf16.bf16.f32 "
        "{%0,%1,%2,%3}, {%4,%5,%6,%7}, {%8,%9}, {%0,%1,%2,%3};"
        : "+f"(d[0]), "+f"(d[1]), "+f"(d[2]), "+f"(d[3])
        : "r"(a[0]), "r"(a[1]), "r"(a[2]), "r"(a[3]), "r"(b0), "r"(b1));
}

// ---------------- setup kernels ----------------
__global__ void __launch_bounds__(256) k_pz(const float* __restrict__ xn,
                                            const float* __restrict__ K1,
                                            int nN, int nPB) {
    if (blockIdx.x >= nPB) {
        int i = (blockIdx.x - nPB) * 256 + threadIdx.x;
        if (i < nN) g_deg[i] = 0.0f;
        return;
    }
    __shared__ float Ks[C * CIN];
    __shared__ float xs[CIN * 64];
    int tid = threadIdx.x;
    for (int i = tid; i < C * CIN; i += 256) Ks[i] = K1[i];
    int n0 = blockIdx.x * 64;
    for (int i = tid; i < CIN * 64; i += 256) {
        int k = i >> 6, nl = i & 63;
        int n = n0 + nl;
        xs[i] = (n < nN) ? xn[(long)k * nN + n] : 0.0f;
    }
    __syncthreads();
    int nl = tid & 63;
    int cb = (tid >> 6) * 16;
    float acc[16];
#pragma unroll
    for (int j = 0; j < 16; j++) acc[j] = 0.0f;
    for (int k = 0; k < CIN; k++) {
        float xv = xs[k * 64 + nl];
#pragma unroll
        for (int j = 0; j < 16; j++) acc[j] = fmaf(Ks[(cb + j) * CIN + k], xv, acc[j]);
    }
    int n = n0 + nl;
    if (n < nN) {
#pragma unroll
        for (int j = 0; j < 16; j++) {
            float v = fmaxf(acc[j], 0.0f);
            g_buf[0][(long)n * C + cb + j] = v;
            g_buf[1][(long)n * C + cb + j] = v;
            g_buf[2][(long)n * C + cb + j] = v;
        }
#pragma unroll
        for (int j = 0; j < 8; j++) {
            float a = fmaxf(acc[2 * j], 0.0f), b = fmaxf(acc[2 * j + 1], 0.0f);
            g_xbf[(long)n * 32 + cb / 2 + j] = bf16x2_pack(a, b);
        }
    }
}

__global__ void k_degree(const int* __restrict__ Jv, int nE) {
    int e = blockIdx.x * blockDim.x + threadIdx.x;
    if (e < nE) atomicAdd(&g_deg[Jv[e]], 1.0f);
}

__global__ void k_Wd(const int* __restrict__ Iv, const int* __restrict__ Jv, int nE) {
    int e = blockIdx.x * blockDim.x + threadIdx.x;
    if (e < nE)
        g_W[e] = rsqrtf(g_deg[Iv[e]] + 1.0f) * rsqrtf(g_deg[Jv[e]] + 1.0f);
}

// A = 2*x_cur - x_old; also refresh bf16 mirror of x_cur
__global__ void k_init(int curI, int oldI, int nxtI, int n4) {
    int i = blockIdx.x * blockDim.x + threadIdx.x;
    if (i >= n4) return;
    float4 a = ((const float4*)g_buf[curI])[i];
    float4 b = ((const float4*)g_buf[oldI])[i];
    ((float4*)g_buf[nxtI])[i] = make_float4(2.0f * a.x - b.x, 2.0f * a.y - b.y,
                                            2.0f * a.z - b.z, 2.0f * a.w - b.w);
    ((uint2*)g_xbf)[i] = make_uint2(bf16x2_pack(a.x, a.y), bf16x2_pack(a.z, a.w));
}

// ---------------- hot kernel ----------------
// PhaseA = idx-prefetch(k+2) + GEMM1(k) interleaved with bf16 x-gather(k+1)
// + tanh->Tt ; sync ; PhaseB = GEMM2(k) + RED scatter(k).
// B fragments rebuilt per-kt from smem Bs via ldmatrix (frees 32 regs -> 3 CTA/SM).
__global__ void __launch_bounds__(256, 3)
k_edge(int aI, const int* __restrict__ Iv, const int* __restrict__ Jv,
       const float* __restrict__ Km, int nE)
{
    extern __shared__ __align__(16) char smem[];
    __nv_bfloat16* GtA = (__nv_bfloat16*)smem;
    __nv_bfloat16* GtB = (__nv_bfloat16*)(smem + GT_BYTES);
    __nv_bfloat16* Tt  = (__nv_bfloat16*)(smem + 2 * GT_BYTES);
    __nv_bfloat16* Bs  = (__nv_bfloat16*)(smem + 3 * GT_BYTES);
    int*   sI = (int*)(smem + 3 * GT_BYTES + BS_BYTES);   // [4][TE]
    int*   sJ = sI + 4 * TE;
    float* sW = (float*)(sJ + 4 * TE);

    int tid = threadIdx.x, lane = tid & 31, wid = tid >> 5;
    int gid = lane >> 2, tig = lane & 3;
    int wm = wid & 3, wn = wid >> 2;
    int mbase = wm * 32, nbase = wn * 32;

    // ---- Bs[n][k] = Km[n*64+k] as bf16, n-major, GSB stride ----
    for (int i = tid; i < C * 32; i += 256) {
        int n = i >> 5, kq = i & 31;
        *(uint32_t*)((char*)Bs + n * (GSB * 2) + kq * 4) =
            bf16x2_pack(Km[n * 64 + 2 * kq], Km[n * 64 + 2 * kq + 1]);
    }

    uint32_t gba = smem_u32(GtA), gbb = smem_u32(GtB), tb = smem_u32(Tt);
    uint32_t bsb = smem_u32(Bs);
    int lrow = (lane & 7) + ((lane >> 3) & 1) * 8;
    int lcol = ((lane >> 4) & 1) * 8;
    // B ldmatrix addresses: group g = lane>>3 selects (ntOff = g>>1, khalf = g&1).
    // matrix m of ldsm4 -> rows n = nbase + (ntA+ntOff)*8 + (lane&7), k = kt*16 + khalf*8
    int bg = lane >> 3;
    uint32_t bAddr0 = bsb + (nbase + ((bg >> 1) * 8) + (lane & 7)) * (GSB * 2)
                    + (bg & 1) * 16;                     // nt pair {0,1}
    uint32_t bAddr1 = bAddr0 + 16 * (GSB * 2);           // nt pair {2,3}

    const uint32_t* xb = g_xbf;
    float* A = g_buf[aI];
    long stride = (long)gridDim.x * TE;
    long e0 = (long)blockIdx.x * TE;

    auto load_idx = [&](long eb, int s) {
        if (tid < TE) {
            long e = eb + tid;
            bool ok = e < (long)nE;
            sI[s * TE + tid] = ok ? Iv[e] : 0;
            sJ[s * TE + tid] = ok ? Jv[e] : 0;
            sW[s * TE + tid] = ok ? g_W[e] : 0.0f;
        }
    };

    // ---- prologue ----
    load_idx(e0, 0);
    load_idx(e0 + stride, 1);
    __syncthreads();
    {
        int eb = wid * 16;
#pragma unroll 4
        for (int el = 0; el < 16; el++) {
            int e = eb + el;
            uint32_t w2 = bf16x2_pack(sW[e], sW[e]);
            uint32_t xi = xb[(long)sI[e] * 32 + lane];
            uint32_t xj = xb[(long)sJ[e] * 32 + lane];
            *(uint32_t*)((char*)GtA + e * (GSB * 2) + lane * 4) = gdiff(xi, xj, w2);
        }
    }

    int s0 = 0;
    int curbuf = 0;
    for (; e0 < nE; e0 += stride) {
        int s1 = (s0 + 1) & 3, s2 = (s0 + 2) & 3;
        uint32_t gcur = curbuf ? gbb : gba;
        char* gnext = (char*)(curbuf ? GtA : GtB);
        __syncthreads();
        // ---- Phase A ----
        load_idx(e0 + 2 * stride, s2);

        float acc[2][4][4];
#pragma unroll
        for (int mt = 0; mt < 2; mt++)
#pragma unroll
            for (int nt = 0; nt < 4; nt++)
#pragma unroll
                for (int q = 0; q < 4; q++) acc[mt][nt][q] = 0.0f;

        const int* sIc = sI + s1 * TE;
        const int* sJc = sJ + s1 * TE;
        const float* sWc = sW + s1 * TE;
        int ebg = wid * 16;
        uint32_t xiu[8], xju[8];
        // wave 0 loads (edges 0-7, tile k+1)
#pragma unroll
        for (int el = 0; el < 8; el++) {
            int e = ebg + el;
            xiu[el] = xb[(long)sIc[e] * 32 + lane];
            xju[el] = xb[(long)sJc[e] * 32 + lane];
        }
        // GEMM1 kt = 0,1
#pragma unroll
        for (int kt = 0; kt < 2; kt++) {
            uint32_t b01[4], b23[4];
            ldsm4(b01, bAddr0 + kt * 32);
            ldsm4(b23, bAddr1 + kt * 32);
#pragma unroll
            for (int mt = 0; mt < 2; mt++) {
                uint32_t af[4];
                ldsm4(af, gcur + (mbase + mt * 16 + lrow) * (GSB * 2)
                              + (kt * 16 + lcol) * 2);
                mma_bf16(acc[mt][0], af, b01[0], b01[1]);
                mma_bf16(acc[mt][1], af, b01[2], b01[3]);
                mma_bf16(acc[mt][2], af, b23[0], b23[1]);
                mma_bf16(acc[mt][3], af, b23[2], b23[3]);
            }
        }
        // store wave 0
#pragma unroll
        for (int el = 0; el < 8; el++) {
            int e = ebg + el;
            uint32_t w2 = bf16x2_pack(sWc[e], sWc[e]);
            *(uint32_t*)(gnext + e * (GSB * 2) + lane * 4) = gdiff(xiu[el], xju[el], w2);
        }
        // wave 1 loads (edges 8-15)
#pragma unroll
        for (int el = 0; el < 8; el++) {
            int e = ebg + 8 + el;
            xiu[el] = xb[(long)sIc[e] * 32 + lane];
            xju[el] = xb[(long)sJc[e] * 32 + lane];
        }
        // GEMM1 kt = 2,3
#pragma unroll
        for (int kt = 2; kt < 4; kt++) {
            uint32_t b01[4], b23[4];
            ldsm4(b01, bAddr0 + kt * 32);
            ldsm4(b23, bAddr1 + kt * 32);
#pragma unroll
            for (int mt = 0; mt < 2; mt++) {
                uint32_t af[4];
                ldsm4(af, gcur + (mbase + mt * 16 + lrow) * (GSB * 2)
                              + (kt * 16 + lcol) * 2);
                mma_bf16(acc[mt][0], af, b01[0], b01[1]);
                mma_bf16(acc[mt][1], af, b01[2], b01[3]);
                mma_bf16(acc[mt][2], af, b23[0], b23[1]);
                mma_bf16(acc[mt][3], af, b23[2], b23[3]);
            }
        }
        // store wave 1
#pragma unroll
        for (int el = 0; el < 8; el++) {
            int e = ebg + 8 + el;
            uint32_t w2 = bf16x2_pack(sWc[e], sWc[e]);
            *(uint32_t*)(gnext + e * (GSB * 2) + lane * 4) = gdiff(xiu[el], xju[el], w2);
        }
        // tanh -> Tt
#pragma unroll
        for (int mt = 0; mt < 2; mt++) {
            int er = mbase + mt * 16 + gid;
#pragma unroll
            for (int nt = 0; nt < 4; nt++) {
                int o = nbase + nt * 8 + tig * 2;
                *(uint32_t*)((char*)Tt + er * (GSB * 2) + o * 2) =
                    bf16x2_pack(tanh_fast(acc[mt][nt][0]), tanh_fast(acc[mt][nt][1]));
                *(uint32_t*)((char*)Tt + (er + 8) * (GSB * 2) + o * 2) =
                    bf16x2_pack(tanh_fast(acc[mt][nt][2]), tanh_fast(acc[mt][nt][3]));
            }
        }
        __syncthreads();
        // ---- Phase B: GEMM2 + scatter ----
#pragma unroll
        for (int mt = 0; mt < 2; mt++)
#pragma unroll
            for (int nt = 0; nt < 4; nt++)
#pragma unroll
                for (int q = 0; q < 4; q++) acc[mt][nt][q] = 0.0f;
#pragma unroll
        for (int kt = 0; kt < 4; kt++) {
            uint32_t b01[4], b23[4];
            ldsm4(b01, bAddr0 + kt * 32);
            ldsm4(b23, bAddr1 + kt * 32);
#pragma unroll
            for (int mt = 0; mt < 2; mt++) {
                uint32_t af[4];
                ldsm4(af, tb + (mbase + mt * 16 + lrow) * (GSB * 2)
                             + (kt * 16 + lcol) * 2);
                mma_bf16(acc[mt][0], af, b01[0], b01[1]);
                mma_bf16(acc[mt][1], af, b01[2], b01[3]);
                mma_bf16(acc[mt][2], af, b23[0], b23[1]);
                mma_bf16(acc[mt][3], af, b23[2], b23[3]);
            }
        }
        const int* sIs = sI + s0 * TE;
        const int* sJs = sJ + s0 * TE;
        const float* sWs = sW + s0 * TE;
#pragma unroll
        for (int mt = 0; mt < 2; mt++) {
#pragma unroll
            for (int half = 0; half < 2; half++) {
                int er = mbase + mt * 16 + gid + half * 8;
                float s = H2f * sWs[er];
                long ni = sIs[er], nj = sJs[er];
                float* pi = A + ni * 64;
                float* pj = A + nj * 64;
#pragma unroll
                for (int nt = 0; nt < 4; nt++) {
                    int c = nbase + nt * 8 + tig * 2;
                    float v0 = s * acc[mt][nt][2 * half];
                    float v1 = s * acc[mt][nt][2 * half + 1];
                    asm volatile("red.global.add.v2.f32 [%0], {%1, %2};"
                                 :: "l"(pi + c), "f"(-v0), "f"(-v1) : "memory");
                    asm volatile("red.global.add.v2.f32 [%0], {%1, %2};"
                                 :: "l"(pj + c), "f"(v0), "f"(v1) : "memory");
                }
            }
        }
        s0 = s1;
        curbuf ^= 1;
    }
}

// out[n][o] = sum_c KNclose[o][c] * x[n][c]
__global__ void __launch_bounds__(128) k_out(int xIdx, const float* __restrict__ KNc,
                                             float* __restrict__ out, int nN, int nOut) {
    __shared__ float Ks[40 * C];
    for (int i = threadIdx.x; i < nOut * C; i += 128) Ks[i] = KNc[i];
    __syncthreads();
    int n = blockIdx.x * 128 + threadIdx.x;
    if (n >= nN) return;
    const float* xr = g_buf[xIdx] + (long)n * C;
    float xv[C];
#pragma unroll
    for (int q = 0; q < C / 4; q++) {
        float4 v = ((const float4*)xr)[q];
        xv[4 * q] = v.x; xv[4 * q + 1] = v.y; xv[4 * q + 2] = v.z; xv[4 * q + 3] = v.w;
    }
    for (int o = 0; o < nOut; o++) {
        float acc = 0.0f;
#pragma unroll
        for (int c = 0; c < C; c++) acc = fmaf(Ks[o * C + c], xv[c], acc);
        out[(long)n * nOut + o] = acc;
    }
}

extern "C" void kernel_launch(void* const* d_in, const int* in_sizes, int n_in,
                              void* d_out, int out_size) {
    const float* xn = (const float*)d_in[0];
    const int* Iv = (const int*)d_in[1];
    const int* Jv = (const int*)d_in[2];
    int idx = 3;
    if (n_in >= 7 && in_sizes[3] == 1) idx = 4;   // skip scalar n_nodes input
    const float* K1  = (const float*)d_in[idx];
    const float* KN2 = (const float*)d_in[idx + 1];
    const float* KNc = (const float*)d_in[idx + 2];
    int nE = in_sizes[1];
    int nN = in_sizes[0] / CIN;
    int nLayer = in_sizes[idx + 1] / (C * C);
    int nOut = in_sizes[idx + 2] / C;
    float* out = (float*)d_out;

    cudaFuncSetAttribute(k_edge, cudaFuncAttributeMaxDynamicSharedMemorySize,
                         SMEM_EDGE);

    int nPB = (nN + 63) / 64;
    int nZB = (nN + 255) / 256;
    k_pz<<<nPB + nZB, 256>>>(xn, K1, nN, nPB);            // launch 0
    k_degree<<<(nE + 255) / 256, 256>>>(Jv, nE);          // launch 1
    k_Wd<<<(nE + 255) / 256, 256>>>(Iv, Jv, nE);          // launch 2

    int cur = 0, old = 1, nxt = 2;
    int n4 = nN * C / 4;
    for (int l = 0; l < nLayer; l++) {
        if (l > 0)
            k_init<<<(n4 + 255) / 256, 256>>>(cur, old, nxt, n4);
        k_edge<<<456, 256, SMEM_EDGE>>>(nxt, Iv, Jv, KN2 + (long)l * C * C, nE);
        int t = old; old = cur; cur = nxt; nxt = t;
    }
    k_out<<<(nN + 127) / 128, 128>>>(cur, KNc, out, nN, nOut);
}

// round 11
// speedup vs baseline: 1.0472x; 1.0472x over previous
#include <cuda_runtime.h>
#include <cuda_bf16.h>
#include <cstdint>

#define CIN 128
#define C 64
#define H2f 0.01f
#define NNODES 50000
#define NEDGES 800000
#define TE 128
#define GSB 72          // smem tile row stride in bf16 (144B)

#define GT_BYTES (TE * GSB * 2)
#define BS_BYTES (C * GSB * 2)
#define SMEM_EDGE (3 * GT_BYTES + BS_BYTES + 4 * TE * 12)

__device__ float g_deg[NNODES];
__device__ float g_W[NEDGES];
__device__ float g_buf[3][(long)NNODES * C];
__device__ uint32_t g_xbf[(long)NNODES * C / 2];   // bf16 mirror of x_cur

// ---------------- helpers ----------------
__device__ __forceinline__ uint32_t smem_u32(const void* p) {
    uint32_t a;
    asm("{ .reg .u64 t; cvta.to.shared.u64 t, %1; cvt.u32.u64 %0, t; }"
        : "=r"(a) : "l"(p));
    return a;
}
__device__ __forceinline__ float tanh_fast(float x) {
    float y;
    asm("tanh.approx.f32 %0, %1;" : "=f"(y) : "f"(x));
    return y;
}
// pack bf16x2: lo = a, hi = b
__device__ __forceinline__ uint32_t bf16x2_pack(float a, float b) {
    uint32_t r;
    asm("cvt.rn.satfinite.bf16x2.f32 %0, %1, %2;" : "=r"(r) : "f"(b), "f"(a));
    return r;
}
// g = w2 * (xi - xj), all bf16x2 packed in u32
__device__ __forceinline__ uint32_t gdiff(uint32_t xi, uint32_t xj, uint32_t w2) {
    __nv_bfloat162 a = *(__nv_bfloat162*)&xi;
    __nv_bfloat162 b = *(__nv_bfloat162*)&xj;
    __nv_bfloat162 w = *(__nv_bfloat162*)&w2;
    __nv_bfloat162 r = __hmul2(w, __hsub2(a, b));
    return *(uint32_t*)&r;
}
__device__ __forceinline__ void ldsm4(uint32_t (&r)[4], uint32_t addr) {
    asm volatile("ldmatrix.sync.aligned.m8n8.x4.shared.b16 {%0,%1,%2,%3}, [%4];"
        : "=r"(r[0]), "=r"(r[1]), "=r"(r[2]), "=r"(r[3]) : "r"(addr));
}
__device__ __forceinline__ void mma_bf16(float (&d)[4], const uint32_t (&a)[4],
                                         uint32_t b0, uint32_t b1) {
    asm volatile("mma.sync.aligned.m16n8k16.row.col.f32.bf16.bf16.f32 "
        "{%0,%1,%2,%3}, {%4,%5,%6,%7}, {%8,%9}, {%0,%1,%2,%3};"
        : "+f"(d[0]), "+f"(d[1]), "+f"(d[2]), "+f"(d[3])
        : "r"(a[0]), "r"(a[1]), "r"(a[2]), "r"(a[3]), "r"(b0), "r"(b1));
}
// 64-thread pair barrier (ids 0..3, one per wm)
__device__ __forceinline__ void pair_bar(int id) {
    asm volatile("bar.sync %0, 64;" :: "r"(id) : "memory");
}

// ---------------- setup kernels ----------------
__global__ void __launch_bounds__(256) k_pz(const float* __restrict__ xn,
                                            const float* __restrict__ K1,
                                            int nN, int nPB) {
    if (blockIdx.x >= nPB) {
        int i = (blockIdx.x - nPB) * 256 + threadIdx.x;
        if (i < nN) g_deg[i] = 0.0f;
        return;
    }
    __shared__ float Ks[C * CIN];
    __shared__ float xs[CIN * 64];
    int tid = threadIdx.x;
    for (int i = tid; i < C * CIN; i += 256) Ks[i] = K1[i];
    int n0 = blockIdx.x * 64;
    for (int i = tid; i < CIN * 64; i += 256) {
        int k = i >> 6, nl = i & 63;
        int n = n0 + nl;
        xs[i] = (n < nN) ? xn[(long)k * nN + n] : 0.0f;
    }
    __syncthreads();
    int nl = tid & 63;
    int cb = (tid >> 6) * 16;
    float acc[16];
#pragma unroll
    for (int j = 0; j < 16; j++) acc[j] = 0.0f;
    for (int k = 0; k < CIN; k++) {
        float xv = xs[k * 64 + nl];
#pragma unroll
        for (int j = 0; j < 16; j++) acc[j] = fmaf(Ks[(cb + j) * CIN + k], xv, acc[j]);
    }
    int n = n0 + nl;
    if (n < nN) {
#pragma unroll
        for (int j = 0; j < 16; j++) {
            float v = fmaxf(acc[j], 0.0f);
            g_buf[0][(long)n * C + cb + j] = v;
            g_buf[1][(long)n * C + cb + j] = v;
            g_buf[2][(long)n * C + cb + j] = v;
        }
#pragma unroll
        for (int j = 0; j < 8; j++) {
            float a = fmaxf(acc[2 * j], 0.0f), b = fmaxf(acc[2 * j + 1], 0.0f);
            g_xbf[(long)n * 32 + cb / 2 + j] = bf16x2_pack(a, b);
        }
    }
}

__global__ void k_degree(const int* __restrict__ Jv, int nE) {
    int e = blockIdx.x * blockDim.x + threadIdx.x;
    if (e < nE) atomicAdd(&g_deg[Jv[e]], 1.0f);
}

__global__ void k_Wd(const int* __restrict__ Iv, const int* __restrict__ Jv, int nE) {
    int e = blockIdx.x * blockDim.x + threadIdx.x;
    if (e < nE)
        g_W[e] = rsqrtf(g_deg[Iv[e]] + 1.0f) * rsqrtf(g_deg[Jv[e]] + 1.0f);
}

// A = 2*x_cur - x_old; also refresh bf16 mirror of x_cur
__global__ void k_init(int curI, int oldI, int nxtI, int n4) {
    int i = blockIdx.x * blockDim.x + threadIdx.x;
    if (i >= n4) return;
    float4 a = ((const float4*)g_buf[curI])[i];
    float4 b = ((const float4*)g_buf[oldI])[i];
    ((float4*)g_buf[nxtI])[i] = make_float4(2.0f * a.x - b.x, 2.0f * a.y - b.y,
                                            2.0f * a.z - b.z, 2.0f * a.w - b.w);
    ((uint2*)g_xbf)[i] = make_uint2(bf16x2_pack(a.x, a.y), bf16x2_pack(a.z, a.w));
}

// ---------------- hot kernel ----------------
// CTA = 4 INDEPENDENT warp pairs (wm = 0..3); pair handles 32 edges/iter with
// its own 64-thread barrier. All cross-warp smem deps are pair-local:
// Gt/Tt rows [wm*32, wm*32+32), idx slots likewise. Pipeline per pair:
// bar -> PhaseA(idx prefetch + gather k+1 interleaved with GEMM1 k + tanh)
// -> bar -> PhaseB(GEMM2 + RED scatter).
__global__ void __launch_bounds__(256, 3)
k_edge(int aI, const int* __restrict__ Iv, const int* __restrict__ Jv,
       const float* __restrict__ Km, int nE)
{
    extern __shared__ __align__(16) char smem[];
    __nv_bfloat16* GtA = (__nv_bfloat16*)smem;
    __nv_bfloat16* GtB = (__nv_bfloat16*)(smem + GT_BYTES);
    __nv_bfloat16* Tt  = (__nv_bfloat16*)(smem + 2 * GT_BYTES);
    __nv_bfloat16* Bs  = (__nv_bfloat16*)(smem + 3 * GT_BYTES);
    int*   sI = (int*)(smem + 3 * GT_BYTES + BS_BYTES);   // [4][TE]
    int*   sJ = sI + 4 * TE;
    float* sW = (float*)(sJ + 4 * TE);

    int tid = threadIdx.x, lane = tid & 31, wid = tid >> 5;
    int gid = lane >> 2, tig = lane & 3;
    int wm = wid & 3, wn = wid >> 2;
    int mbase = wm * 32, nbase = wn * 32;

    // ---- Bs[n][k] = Km[n*64+k] as bf16, n-major, GSB stride ----
    for (int i = tid; i < C * 32; i += 256) {
        int n = i >> 5, kq = i & 31;
        *(uint32_t*)((char*)Bs + n * (GSB * 2) + kq * 4) =
            bf16x2_pack(Km[n * 64 + 2 * kq], Km[n * 64 + 2 * kq + 1]);
    }

    uint32_t gba = smem_u32(GtA), gbb = smem_u32(GtB), tb = smem_u32(Tt);
    uint32_t bsb = smem_u32(Bs);
    int lrow = (lane & 7) + ((lane >> 3) & 1) * 8;
    int lcol = ((lane >> 4) & 1) * 8;
    int bg = lane >> 3;
    uint32_t bAddr0 = bsb + (nbase + ((bg >> 1) * 8) + (lane & 7)) * (GSB * 2)
                    + (bg & 1) * 16;                     // nt pair {0,1}
    uint32_t bAddr1 = bAddr0 + 16 * (GSB * 2);           // nt pair {2,3}

    const uint32_t* xb = g_xbf;
    float* A = g_buf[aI];
    long stride = (long)gridDim.x * TE;
    long e0 = (long)blockIdx.x * TE;

    // pair-local idx loader: wn==0 warp loads this pair's 32 edges
    auto load_idx = [&](long eb, int s) {
        if (wn == 0) {
            long e = eb + mbase + lane;
            bool ok = e < (long)nE;
            int t = s * TE + mbase + lane;
            sI[t] = ok ? Iv[e] : 0;
            sJ[t] = ok ? Jv[e] : 0;
            sW[t] = ok ? g_W[e] : 0.0f;
        }
    };

    // ---- prologue: idx slots 0,1; gather tile 0 into GtA (pair rows) ----
    load_idx(e0, 0);
    load_idx(e0 + stride, 1);
    __syncthreads();                    // Bs + initial idx (block-wide, once)
    {
        int eb = mbase + wn * 16;
#pragma unroll 4
        for (int el = 0; el < 16; el++) {
            int e = eb + el;
            uint32_t w2 = bf16x2_pack(sW[e], sW[e]);
            uint32_t xi = xb[(long)sI[e] * 32 + lane];
            uint32_t xj = xb[(long)sJ[e] * 32 + lane];
            *(uint32_t*)((char*)GtA + e * (GSB * 2) + lane * 4) = gdiff(xi, xj, w2);
        }
    }

    int s0 = 0;
    int curbuf = 0;
    for (; e0 < nE; e0 += stride) {
        int s1 = (s0 + 1) & 3, s2 = (s0 + 2) & 3;
        uint32_t gcur = curbuf ? gbb : gba;
        char* gnext = (char*)(curbuf ? GtA : GtB);
        pair_bar(wm);                   // pair's Gt/Tt consumed, idx ready
        // ---- Phase A ----
        load_idx(e0 + 2 * stride, s2);

        float acc[2][4][4];
#pragma unroll
        for (int mt = 0; mt < 2; mt++)
#pragma unroll
            for (int nt = 0; nt < 4; nt++)
#pragma unroll
                for (int q = 0; q < 4; q++) acc[mt][nt][q] = 0.0f;

        const int* sIc = sI + s1 * TE;
        const int* sJc = sJ + s1 * TE;
        const float* sWc = sW + s1 * TE;
        int ebg = mbase + wn * 16;
        uint32_t xiu[8], xju[8];
        // wave 0 loads (this warp's edges 0-7, tile k+1)
#pragma unroll
        for (int el = 0; el < 8; el++) {
            int e = ebg + el;
            xiu[el] = xb[(long)sIc[e] * 32 + lane];
            xju[el] = xb[(long)sJc[e] * 32 + lane];
        }
        // GEMM1 kt = 0,1
#pragma unroll
        for (int kt = 0; kt < 2; kt++) {
            uint32_t b01[4], b23[4];
            ldsm4(b01, bAddr0 + kt * 32);
            ldsm4(b23, bAddr1 + kt * 32);
#pragma unroll
            for (int mt = 0; mt < 2; mt++) {
                uint32_t af[4];
                ldsm4(af, gcur + (mbase + mt * 16 + lrow) * (GSB * 2)
                              + (kt * 16 + lcol) * 2);
                mma_bf16(acc[mt][0], af, b01[0], b01[1]);
                mma_bf16(acc[mt][1], af, b01[2], b01[3]);
                mma_bf16(acc[mt][2], af, b23[0], b23[1]);
                mma_bf16(acc[mt][3], af, b23[2], b23[3]);
            }
        }
        // store wave 0
#pragma unroll
        for (int el = 0; el < 8; el++) {
            int e = ebg + el;
            uint32_t w2 = bf16x2_pack(sWc[e], sWc[e]);
            *(uint32_t*)(gnext + e * (GSB * 2) + lane * 4) = gdiff(xiu[el], xju[el], w2);
        }
        // wave 1 loads (edges 8-15)
#pragma unroll
        for (int el = 0; el < 8; el++) {
            int e = ebg + 8 + el;
            xiu[el] = xb[(long)sIc[e] * 32 + lane];
            xju[el] = xb[(long)sJc[e] * 32 + lane];
        }
        // GEMM1 kt = 2,3
#pragma unroll
        for (int kt = 2; kt < 4; kt++) {
            uint32_t b01[4], b23[4];
            ldsm4(b01, bAddr0 + kt * 32);
            ldsm4(b23, bAddr1 + kt * 32);
#pragma unroll
            for (int mt = 0; mt < 2; mt++) {
                uint32_t af[4];
                ldsm4(af, gcur + (mbase + mt * 16 + lrow) * (GSB * 2)
                              + (kt * 16 + lcol) * 2);
                mma_bf16(acc[mt][0], af, b01[0], b01[1]);
                mma_bf16(acc[mt][1], af, b01[2], b01[3]);
                mma_bf16(acc[mt][2], af, b23[0], b23[1]);
                mma_bf16(acc[mt][3], af, b23[2], b23[3]);
            }
        }
        // store wave 1
#pragma unroll
        for (int el = 0; el < 8; el++) {
            int e = ebg + 8 + el;
            uint32_t w2 = bf16x2_pack(sWc[e], sWc[e]);
            *(uint32_t*)(gnext + e * (GSB * 2) + lane * 4) = gdiff(xiu[el], xju[el], w2);
        }
        // tanh -> Tt (pair rows, this warp's column half)
#pragma unroll
        for (int mt = 0; mt < 2; mt++) {
            int er = mbase + mt * 16 + gid;
#pragma unroll
            for (int nt = 0; nt < 4; nt++) {
                int o = nbase + nt * 8 + tig * 2;
                *(uint32_t*)((char*)Tt + er * (GSB * 2) + o * 2) =
                    bf16x2_pack(tanh_fast(acc[mt][nt][0]), tanh_fast(acc[mt][nt][1]));
                *(uint32_t*)((char*)Tt + (er + 8) * (GSB * 2) + o * 2) =
                    bf16x2_pack(tanh_fast(acc[mt][nt][2]), tanh_fast(acc[mt][nt][3]));
            }
        }
        pair_bar(wm);                   // Tt pair rows complete (both halves)
        // ---- Phase B: GEMM2 + scatter ----
#pragma unroll
        for (int mt = 0; mt < 2; mt++)
#pragma unroll
            for (int nt = 0; nt < 4; nt++)
#pragma unroll
                for (int q = 0; q < 4; q++) acc[mt][nt][q] = 0.0f;
#pragma unroll
        for (int kt = 0; kt < 4; kt++) {
            uint32_t b01[4], b23[4];
            ldsm4(b01, bAddr0 + kt * 32);
            ldsm4(b23, bAddr1 + kt * 32);
#pragma unroll
            for (int mt = 0; mt < 2; mt++) {
                uint32_t af[4];
                ldsm4(af, tb + (mbase + mt * 16 + lrow) * (GSB * 2)
                             + (kt * 16 + lcol) * 2);
                mma_bf16(acc[mt][0], af, b01[0], b01[1]);
                mma_bf16(acc[mt][1], af, b01[2], b01[3]);
                mma_bf16(acc[mt][2], af, b23[0], b23[1]);
                mma_bf16(acc[mt][3], af, b23[2], b23[3]);
            }
        }
        const int* sIs = sI + s0 * TE;
        const int* sJs = sJ + s0 * TE;
        const float* sWs = sW + s0 * TE;
#pragma unroll
        for (int mt = 0; mt < 2; mt++) {
#pragma unroll
            for (int half = 0; half < 2; half++) {
                int er = mbase + mt * 16 + gid + half * 8;
                float s = H2f * sWs[er];
                long ni = sIs[er], nj = sJs[er];
                float* pi = A + ni * 64;
                float* pj = A + nj * 64;
#pragma unroll
                for (int nt = 0; nt < 4; nt++) {
                    int c = nbase + nt * 8 + tig * 2;
                    float v0 = s * acc[mt][nt][2 * half];
                    float v1 = s * acc[mt][nt][2 * half + 1];
                    asm volatile("red.global.add.v2.f32 [%0], {%1, %2};"
                                 :: "l"(pi + c), "f"(-v0), "f"(-v1) : "memory");
                    asm volatile("red.global.add.v2.f32 [%0], {%1, %2};"
                                 :: "l"(pj + c), "f"(v0), "f"(v1) : "memory");
                }
            }
        }
        s0 = s1;
        curbuf ^= 1;
    }
}

// out[n][o] = sum_c KNclose[o][c] * x[n][c]
__global__ void __launch_bounds__(128) k_out(int xIdx, const float* __restrict__ KNc,
                                             float* __restrict__ out, int nN, int nOut) {
    __shared__ float Ks[40 * C];
    for (int i = threadIdx.x; i < nOut * C; i += 128) Ks[i] = KNc[i];
    __syncthreads();
    int n = blockIdx.x * 128 + threadIdx.x;
    if (n >= nN) return;
    const float* xr = g_buf[xIdx] + (long)n * C;
    float xv[C];
#pragma unroll
    for (int q = 0; q < C / 4; q++) {
        float4 v = ((const float4*)xr)[q];
        xv[4 * q] = v.x; xv[4 * q + 1] = v.y; xv[4 * q + 2] = v.z; xv[4 * q + 3] = v.w;
    }
    for (int o = 0; o < nOut; o++) {
        float acc = 0.0f;
#pragma unroll
        for (int c = 0; c < C; c++) acc = fmaf(Ks[o * C + c], xv[c], acc);
        out[(long)n * nOut + o] = acc;
    }
}

extern "C" void kernel_launch(void* const* d_in, const int* in_sizes, int n_in,
                              void* d_out, int out_size) {
    const float* xn = (const float*)d_in[0];
    const int* Iv = (const int*)d_in[1];
    const int* Jv = (const int*)d_in[2];
    int idx = 3;
    if (n_in >= 7 && in_sizes[3] == 1) idx = 4;   // skip scalar n_nodes input
    const float* K1  = (const float*)d_in[idx];
    const float* KN2 = (const float*)d_in[idx + 1];
    const float* KNc = (const float*)d_in[idx + 2];
    int nE = in_sizes[1];
    int nN = in_sizes[0] / CIN;
    int nLayer = in_sizes[idx + 1] / (C * C);
    int nOut = in_sizes[idx + 2] / C;
    float* out = (float*)d_out;

    cudaFuncSetAttribute(k_edge, cudaFuncAttributeMaxDynamicSharedMemorySize,
                         SMEM_EDGE);

    int nPB = (nN + 63) / 64;
    int nZB = (nN + 255) / 256;
    k_pz<<<nPB + nZB, 256>>>(xn, K1, nN, nPB);            // launch 0
    k_degree<<<(nE + 255) / 256, 256>>>(Jv, nE);          // launch 1
    k_Wd<<<(nE + 255) / 256, 256>>>(Iv, Jv, nE);          // launch 2

    int cur = 0, old = 1, nxt = 2;
    int n4 = nN * C / 4;
    for (int l = 0; l < nLayer; l++) {
        if (l > 0)
            k_init<<<(n4 + 255) / 256, 256>>>(cur, old, nxt, n4);
        k_edge<<<456, 256, SMEM_EDGE>>>(nxt, Iv, Jv, KN2 + (long)l * C * C, nE);
        int t = old; old = cur; cur = nxt; nxt = t;
    }
    k_out<<<(nN + 127) / 128, 128>>>(cur, KNc, out, nN, nOut);
}

// round 13
// speedup vs baseline: 1.0517x; 1.0044x over previous
#include <cuda_runtime.h>
#include <cuda_bf16.h>
#include <cstdint>

#define CIN 128
#define C 64
#define H2f 0.01f
#define NNODES 50000
#define NEDGES 800000
#define TE 128
#define GSB 72          // smem tile row stride in bf16 (144B)

#define GT_BYTES (TE * GSB * 2)
#define BS_BYTES (C * GSB * 2)
#define SMEM_EDGE (3 * GT_BYTES + BS_BYTES + 4 * TE * 12)
#define NB 456

__device__ float g_deg[NNODES];
__device__ float g_W[NEDGES];
__device__ float g_buf[3][(long)NNODES * C];
__device__ uint32_t g_xbf[(long)NNODES * C / 2];   // bf16 mirror of x_cur
__device__ unsigned g_ctr = 0;
__device__ unsigned g_epoch = 0;

// ---------------- helpers ----------------
__device__ __forceinline__ uint32_t smem_u32(const void* p) {
    uint32_t a;
    asm("{ .reg .u64 t; cvta.to.shared.u64 t, %1; cvt.u32.u64 %0, t; }"
        : "=r"(a) : "l"(p));
    return a;
}
__device__ __forceinline__ float tanh_fast(float x) {
    float y;
    asm("tanh.approx.f32 %0, %1;" : "=f"(y) : "f"(x));
    return y;
}
// pack bf16x2: lo = a, hi = b
__device__ __forceinline__ uint32_t bf16x2_pack(float a, float b) {
    uint32_t r;
    asm("cvt.rn.satfinite.bf16x2.f32 %0, %1, %2;" : "=r"(r) : "f"(b), "f"(a));
    return r;
}
// g = w2 * (xi - xj), all bf16x2 packed in u32
__device__ __forceinline__ uint32_t gdiff(uint32_t xi, uint32_t xj, uint32_t w2) {
    __nv_bfloat162 a = *(__nv_bfloat162*)&xi;
    __nv_bfloat162 b = *(__nv_bfloat162*)&xj;
    __nv_bfloat162 w = *(__nv_bfloat162*)&w2;
    __nv_bfloat162 r = __hmul2(w, __hsub2(a, b));
    return *(uint32_t*)&r;
}
__device__ __forceinline__ void ldsm4(uint32_t (&r)[4], uint32_t addr) {
    asm volatile("ldmatrix.sync.aligned.m8n8.x4.shared.b16 {%0,%1,%2,%3}, [%4];"
        : "=r"(r[0]), "=r"(r[1]), "=r"(r[2]), "=r"(r[3]) : "r"(addr));
}
__device__ __forceinline__ void mma_bf16(float (&d)[4], const uint32_t (&a)[4],
                                         uint32_t b0, uint32_t b1) {
    asm volatile("mma.sync.aligned.m16n8k16.row.col.f32.bf16.bf16.f32 "
        "{%0,%1,%2,%3}, {%4,%5,%6,%7}, {%8,%9}, {%0,%1,%2,%3};"
        : "+f"(d[0]), "+f"(d[1]), "+f"(d[2]), "+f"(d[3])
        : "r"(a[0]), "r"(a[1]), "r"(a[2]), "r"(a[3]), "r"(b0), "r"(b1));
}
// 64-thread pair barrier, ids 1..4 (id 0 reserved for __syncthreads!)
__device__ __forceinline__ void pair_bar(int wm) {
    asm volatile("bar.sync %0, 64;" :: "r"(wm + 1) : "memory");
}
// grid-wide barrier (all NB blocks resident; sense-reversing epoch)
__device__ __forceinline__ void grid_sync() {
    __syncthreads();
    if (threadIdx.x == 0) {
        __threadfence();
        unsigned e = atomicAdd(&g_epoch, 0u);
        if (atomicAdd(&g_ctr, 1u) == (unsigned)(gridDim.x - 1)) {
            g_ctr = 0;
            __threadfence();
            atomicExch(&g_epoch, e + 1u);
        } else {
            while (atomicAdd(&g_epoch, 0u) == e) __nanosleep(64);
        }
        __threadfence();
    }
    __syncthreads();
}

// ---------------- setup kernels ----------------
__global__ void __launch_bounds__(256) k_pz(const float* __restrict__ xn,
                                            const float* __restrict__ K1,
                                            int nN, int nPB) {
    if (blockIdx.x >= nPB) {
        int i = (blockIdx.x - nPB) * 256 + threadIdx.x;
        if (i < nN) g_deg[i] = 0.0f;
        return;
    }
    __shared__ float Ks[C * CIN];
    __shared__ float xs[CIN * 64];
    int tid = threadIdx.x;
    for (int i = tid; i < C * CIN; i += 256) Ks[i] = K1[i];
    int n0 = blockIdx.x * 64;
    for (int i = tid; i < CIN * 64; i += 256) {
        int k = i >> 6, nl = i & 63;
        int n = n0 + nl;
        xs[i] = (n < nN) ? xn[(long)k * nN + n] : 0.0f;
    }
    __syncthreads();
    int nl = tid & 63;
    int cb = (tid >> 6) * 16;
    float acc[16];
#pragma unroll
    for (int j = 0; j < 16; j++) acc[j] = 0.0f;
    for (int k = 0; k < CIN; k++) {
        float xv = xs[k * 64 + nl];
#pragma unroll
        for (int j = 0; j < 16; j++) acc[j] = fmaf(Ks[(cb + j) * CIN + k], xv, acc[j]);
    }
    int n = n0 + nl;
    if (n < nN) {
#pragma unroll
        for (int j = 0; j < 16; j++) {
            float v = fmaxf(acc[j], 0.0f);
            g_buf[0][(long)n * C + cb + j] = v;
            g_buf[1][(long)n * C + cb + j] = v;
            g_buf[2][(long)n * C + cb + j] = v;
        }
#pragma unroll
        for (int j = 0; j < 8; j++) {
            float a = fmaxf(acc[2 * j], 0.0f), b = fmaxf(acc[2 * j + 1], 0.0f);
            g_xbf[(long)n * 32 + cb / 2 + j] = bf16x2_pack(a, b);
        }
    }
}

__global__ void k_degree(const int* __restrict__ Jv, int nE) {
    int e = blockIdx.x * blockDim.x + threadIdx.x;
    if (e < nE) atomicAdd(&g_deg[Jv[e]], 1.0f);
}

__global__ void k_Wd(const int* __restrict__ Iv, const int* __restrict__ Jv, int nE) {
    int e = blockIdx.x * blockDim.x + threadIdx.x;
    if (e < nE)
        g_W[e] = rsqrtf(g_deg[Iv[e]] + 1.0f) * rsqrtf(g_deg[Jv[e]] + 1.0f);
}

// ---------------- persistent multi-layer hot kernel ----------------
// Per layer: edge phase (R11 pair-pipelined body) -> grid_sync -> buffer
// rotation + fused init (A = 2x - x_old, bf16 mirror) -> grid_sync.
__global__ void __launch_bounds__(256, 3)
k_layers(const int* __restrict__ Iv, const int* __restrict__ Jv,
         const float* __restrict__ KN2, int nE, int nN, int nLayer)
{
    extern __shared__ __align__(16) char smem[];
    __nv_bfloat16* GtA = (__nv_bfloat16*)smem;
    __nv_bfloat16* GtB = (__nv_bfloat16*)(smem + GT_BYTES);
    __nv_bfloat16* Tt  = (__nv_bfloat16*)(smem + 2 * GT_BYTES);
    __nv_bfloat16* Bs  = (__nv_bfloat16*)(smem + 3 * GT_BYTES);
    int*   sI = (int*)(smem + 3 * GT_BYTES + BS_BYTES);   // [4][TE]
    int*   sJ = sI + 4 * TE;
    float* sW = (float*)(sJ + 4 * TE);

    int tid = threadIdx.x, lane = tid & 31, wid = tid >> 5;
    int gid = lane >> 2, tig = lane & 3;
    int wm = wid & 3, wn = wid >> 2;
    int mbase = wm * 32, nbase = wn * 32;

    uint32_t gba = smem_u32(GtA), gbb = smem_u32(GtB), tb = smem_u32(Tt);
    uint32_t bsb = smem_u32(Bs);
    int lrow = (lane & 7) + ((lane >> 3) & 1) * 8;
    int lcol = ((lane >> 4) & 1) * 8;
    int bg = lane >> 3;
    uint32_t bAddr0 = bsb + (nbase + ((bg >> 1) * 8) + (lane & 7)) * (GSB * 2)
                    + (bg & 1) * 16;                     // nt pair {0,1}
    uint32_t bAddr1 = bAddr0 + 16 * (GSB * 2);           // nt pair {2,3}

    const uint32_t* xb = g_xbf;
    long stride = (long)gridDim.x * TE;
    int n4 = nN * C / 4;
    int cur = 0, old = 1, nxt = 2;

    for (int l = 0; l < nLayer; l++) {
        const float* Km = KN2 + (long)l * C * C;
        float* A = g_buf[nxt];

        // ---- Bs[n][k] = Km[n*64+k] as bf16 ----
        for (int i = tid; i < C * 32; i += 256) {
            int n = i >> 5, kq = i & 31;
            *(uint32_t*)((char*)Bs + n * (GSB * 2) + kq * 4) =
                bf16x2_pack(Km[n * 64 + 2 * kq], Km[n * 64 + 2 * kq + 1]);
        }

        long e0 = (long)blockIdx.x * TE;
        // pair-local idx loader
        auto load_idx = [&](long eb, int s) {
            if (wn == 0) {
                long e = eb + mbase + lane;
                bool ok = e < (long)nE;
                int t = s * TE + mbase + lane;
                sI[t] = ok ? Iv[e] : 0;
                sJ[t] = ok ? Jv[e] : 0;
                sW[t] = ok ? g_W[e] : 0.0f;
            }
        };

        load_idx(e0, 0);
        load_idx(e0 + stride, 1);
        __syncthreads();                // Bs + initial idx visible block-wide
        {
            int eb = mbase + wn * 16;
#pragma unroll 4
            for (int el = 0; el < 16; el++) {
                int e = eb + el;
                uint32_t w2 = bf16x2_pack(sW[e], sW[e]);
                uint32_t xi = xb[(long)sI[e] * 32 + lane];
                uint32_t xj = xb[(long)sJ[e] * 32 + lane];
                *(uint32_t*)((char*)GtA + e * (GSB * 2) + lane * 4) =
                    gdiff(xi, xj, w2);
            }
        }

        int s0 = 0;
        int curbuf = 0;
        for (; e0 < nE; e0 += stride) {
            int s1 = (s0 + 1) & 3, s2 = (s0 + 2) & 3;
            uint32_t gcur = curbuf ? gbb : gba;
            char* gnext = (char*)(curbuf ? GtA : GtB);
            pair_bar(wm);               // pair's Gt/Tt consumed, idx ready
            // ---- Phase A ----
            load_idx(e0 + 2 * stride, s2);

            float acc[2][4][4];
#pragma unroll
            for (int mt = 0; mt < 2; mt++)
#pragma unroll
                for (int nt = 0; nt < 4; nt++)
#pragma unroll
                    for (int q = 0; q < 4; q++) acc[mt][nt][q] = 0.0f;

            const int* sIc = sI + s1 * TE;
            const int* sJc = sJ + s1 * TE;
            const float* sWc = sW + s1 * TE;
            int ebg = mbase + wn * 16;
            uint32_t xiu[8], xju[8];
            // wave 0 loads (this warp's edges 0-7, tile k+1)
#pragma unroll
            for (int el = 0; el < 8; el++) {
                int e = ebg + el;
                xiu[el] = xb[(long)sIc[e] * 32 + lane];
                xju[el] = xb[(long)sJc[e] * 32 + lane];
            }
            // GEMM1 kt = 0,1
#pragma unroll
            for (int kt = 0; kt < 2; kt++) {
                uint32_t b01[4], b23[4];
                ldsm4(b01, bAddr0 + kt * 32);
                ldsm4(b23, bAddr1 + kt * 32);
#pragma unroll
                for (int mt = 0; mt < 2; mt++) {
                    uint32_t af[4];
                    ldsm4(af, gcur + (mbase + mt * 16 + lrow) * (GSB * 2)
                                  + (kt * 16 + lcol) * 2);
                    mma_bf16(acc[mt][0], af, b01[0], b01[1]);
                    mma_bf16(acc[mt][1], af, b01[2], b01[3]);
                    mma_bf16(acc[mt][2], af, b23[0], b23[1]);
                    mma_bf16(acc[mt][3], af, b23[2], b23[3]);
                }
            }
            // store wave 0
#pragma unroll
            for (int el = 0; el < 8; el++) {
                int e = ebg + el;
                uint32_t w2 = bf16x2_pack(sWc[e], sWc[e]);
                *(uint32_t*)(gnext + e * (GSB * 2) + lane * 4) =
                    gdiff(xiu[el], xju[el], w2);
            }
            // wave 1 loads (edges 8-15)
#pragma unroll
            for (int el = 0; el < 8; el++) {
                int e = ebg + 8 + el;
                xiu[el] = xb[(long)sIc[e] * 32 + lane];
                xju[el] = xb[(long)sJc[e] * 32 + lane];
            }
            // GEMM1 kt = 2,3
#pragma unroll
            for (int kt = 2; kt < 4; kt++) {
                uint32_t b01[4], b23[4];
                ldsm4(b01, bAddr0 + kt * 32);
                ldsm4(b23, bAddr1 + kt * 32);
#pragma unroll
                for (int mt = 0; mt < 2; mt++) {
                    uint32_t af[4];
                    ldsm4(af, gcur + (mbase + mt * 16 + lrow) * (GSB * 2)
                                  + (kt * 16 + lcol) * 2);
                    mma_bf16(acc[mt][0], af, b01[0], b01[1]);
                    mma_bf16(acc[mt][1], af, b01[2], b01[3]);
                    mma_bf16(acc[mt][2], af, b23[0], b23[1]);
                    mma_bf16(acc[mt][3], af, b23[2], b23[3]);
                }
            }
            // store wave 1
#pragma unroll
            for (int el = 0; el < 8; el++) {
                int e = ebg + 8 + el;
                uint32_t w2 = bf16x2_pack(sWc[e], sWc[e]);
                *(uint32_t*)(gnext + e * (GSB * 2) + lane * 4) =
                    gdiff(xiu[el], xju[el], w2);
            }
            // tanh -> Tt (pair rows, this warp's column half)
#pragma unroll
            for (int mt = 0; mt < 2; mt++) {
                int er = mbase + mt * 16 + gid;
#pragma unroll
                for (int nt = 0; nt < 4; nt++) {
                    int o = nbase + nt * 8 + tig * 2;
                    *(uint32_t*)((char*)Tt + er * (GSB * 2) + o * 2) =
                        bf16x2_pack(tanh_fast(acc[mt][nt][0]),
                                    tanh_fast(acc[mt][nt][1]));
                    *(uint32_t*)((char*)Tt + (er + 8) * (GSB * 2) + o * 2) =
                        bf16x2_pack(tanh_fast(acc[mt][nt][2]),
                                    tanh_fast(acc[mt][nt][3]));
                }
            }
            pair_bar(wm);               // Tt pair rows complete (both halves)
            // ---- Phase B: GEMM2 + scatter ----
#pragma unroll
            for (int mt = 0; mt < 2; mt++)
#pragma unroll
                for (int nt = 0; nt < 4; nt++)
#pragma unroll
                    for (int q = 0; q < 4; q++) acc[mt][nt][q] = 0.0f;
#pragma unroll
            for (int kt = 0; kt < 4; kt++) {
                uint32_t b01[4], b23[4];
                ldsm4(b01, bAddr0 + kt * 32);
                ldsm4(b23, bAddr1 + kt * 32);
#pragma unroll
                for (int mt = 0; mt < 2; mt++) {
                    uint32_t af[4];
                    ldsm4(af, tb + (mbase + mt * 16 + lrow) * (GSB * 2)
                                 + (kt * 16 + lcol) * 2);
                    mma_bf16(acc[mt][0], af, b01[0], b01[1]);
                    mma_bf16(acc[mt][1], af, b01[2], b01[3]);
                    mma_bf16(acc[mt][2], af, b23[0], b23[1]);
                    mma_bf16(acc[mt][3], af, b23[2], b23[3]);
                }
            }
            const int* sIs = sI + s0 * TE;
            const int* sJs = sJ + s0 * TE;
            const float* sWs = sW + s0 * TE;
#pragma unroll
            for (int mt = 0; mt < 2; mt++) {
#pragma unroll
                for (int half = 0; half < 2; half++) {
                    int er = mbase + mt * 16 + gid + half * 8;
                    float s = H2f * sWs[er];
                    long ni = sIs[er], nj = sJs[er];
                    float* pi = A + ni * 64;
                    float* pj = A + nj * 64;
#pragma unroll
                    for (int nt = 0; nt < 4; nt++) {
                        int c = nbase + nt * 8 + tig * 2;
                        float v0 = s * acc[mt][nt][2 * half];
                        float v1 = s * acc[mt][nt][2 * half + 1];
                        asm volatile("red.global.add.v2.f32 [%0], {%1, %2};"
                                     :: "l"(pi + c), "f"(-v0), "f"(-v1) : "memory");
                        asm volatile("red.global.add.v2.f32 [%0], {%1, %2};"
                                     :: "l"(pj + c), "f"(v0), "f"(v1) : "memory");
                    }
                }
            }
            s0 = s1;
            curbuf ^= 1;
        }

        // ---- layer boundary ----
        grid_sync();                    // all scatters of layer l complete
        int t = old; old = cur; cur = nxt; nxt = t;
        if (l + 1 < nLayer) {
            const float4* xc = (const float4*)g_buf[cur];
            const float4* xo = (const float4*)g_buf[old];
            float4* An = (float4*)g_buf[nxt];
            uint2* mir = (uint2*)g_xbf;
            for (int i = blockIdx.x * 256 + tid; i < n4; i += gridDim.x * 256) {
                float4 a = xc[i], b = xo[i];
                An[i] = make_float4(2.0f * a.x - b.x, 2.0f * a.y - b.y,
                                    2.0f * a.z - b.z, 2.0f * a.w - b.w);
                mir[i] = make_uint2(bf16x2_pack(a.x, a.y), bf16x2_pack(a.z, a.w));
            }
            grid_sync();                // init complete before next layer
        }
    }
}

// out[n][o] = sum_c KNclose[o][c] * x[n][c]
__global__ void __launch_bounds__(128) k_out(int xIdx, const float* __restrict__ KNc,
                                             float* __restrict__ out, int nN, int nOut) {
    __shared__ float Ks[40 * C];
    for (int i = threadIdx.x; i < nOut * C; i += 128) Ks[i] = KNc[i];
    __syncthreads();
    int n = blockIdx.x * 128 + threadIdx.x;
    if (n >= nN) return;
    const float* xr = g_buf[xIdx] + (long)n * C;
    float xv[C];
#pragma unroll
    for (int q = 0; q < C / 4; q++) {
        float4 v = ((const float4*)xr)[q];
        xv[4 * q] = v.x; xv[4 * q + 1] = v.y; xv[4 * q + 2] = v.z; xv[4 * q + 3] = v.w;
    }
    for (int o = 0; o < nOut; o++) {
        float acc = 0.0f;
#pragma unroll
        for (int c = 0; c < C; c++) acc = fmaf(Ks[o * C + c], xv[c], acc);
        out[(long)n * nOut + o] = acc;
    }
}

extern "C" void kernel_launch(void* const* d_in, const int* in_sizes, int n_in,
                              void* d_out, int out_size) {
    const float* xn = (const float*)d_in[0];
    const int* Iv = (const int*)d_in[1];
    const int* Jv = (const int*)d_in[2];
    int idx = 3;
    if (n_in >= 7 && in_sizes[3] == 1) idx = 4;   // skip scalar n_nodes input
    const float* K1  = (const float*)d_in[idx];
    const float* KN2 = (const float*)d_in[idx + 1];
    const float* KNc = (const float*)d_in[idx + 2];
    int nE = in_sizes[1];
    int nN = in_sizes[0] / CIN;
    int nLayer = in_sizes[idx + 1] / (C * C);
    int nOut = in_sizes[idx + 2] / C;
    float* out = (float*)d_out;

    cudaFuncSetAttribute(k_layers, cudaFuncAttributeMaxDynamicSharedMemorySize,
                         SMEM_EDGE);

    int nPB = (nN + 63) / 64;
    int nZB = (nN + 255) / 256;
    k_pz<<<nPB + nZB, 256>>>(xn, K1, nN, nPB);
    k_degree<<<(nE + 255) / 256, 256>>>(Jv, nE);
    k_Wd<<<(nE + 255) / 256, 256>>>(Iv, Jv, nE);

    k_layers<<<NB, 256, SMEM_EDGE>>>(Iv, Jv, KN2, nE, nN, nLayer);

    // replicate in-kernel buffer rotation to find final cur
    int cur = 0, old = 1, nxt = 2;
    for (int l = 0; l < nLayer; l++) { int t = old; old = cur; cur = nxt; nxt = t; }
    k_out<<<(nN + 127) / 128, 128>>>(cur, KNc, out, nN, nOut);
}

// round 14
// speedup vs baseline: 1.1052x; 1.0509x over previous
#include <cuda_runtime.h>
#include <cuda_bf16.h>
#include <cstdint>

#define CIN 128
#define C 64
#define H2f 0.01f
#define NNODES 50000
#define NEDGES 800000
#define TE 128
#define GSB 72          // smem tile row stride in bf16 (144B)

#define GT_BYTES (TE * GSB * 2)
#define BS_BYTES (C * GSB * 2)
#define SMEM_EDGE (3 * GT_BYTES + BS_BYTES + 4 * TE * 12)
#define NB 456

__device__ float g_deg[NNODES];
__device__ float g_W[NEDGES];
__device__ float g_buf[3][(long)NNODES * C];
__device__ uint32_t g_xbf[(long)NNODES * C / 2];   // bf16 mirror of x_cur
__device__ unsigned g_ctr = 0;
__device__ unsigned g_epoch = 0;

// ---------------- helpers ----------------
__device__ __forceinline__ uint32_t smem_u32(const void* p) {
    uint32_t a;
    asm("{ .reg .u64 t; cvta.to.shared.u64 t, %1; cvt.u32.u64 %0, t; }"
        : "=r"(a) : "l"(p));
    return a;
}
__device__ __forceinline__ float tanh_fast(float x) {
    float y;
    asm("tanh.approx.f32 %0, %1;" : "=f"(y) : "f"(x));
    return y;
}
// pack bf16x2: lo = a, hi = b
__device__ __forceinline__ uint32_t bf16x2_pack(float a, float b) {
    uint32_t r;
    asm("cvt.rn.satfinite.bf16x2.f32 %0, %1, %2;" : "=r"(r) : "f"(b), "f"(a));
    return r;
}
// g = w2 * (xi - xj), all bf16x2 packed in u32
__device__ __forceinline__ uint32_t gdiff(uint32_t xi, uint32_t xj, uint32_t w2) {
    __nv_bfloat162 a = *(__nv_bfloat162*)&xi;
    __nv_bfloat162 b = *(__nv_bfloat162*)&xj;
    __nv_bfloat162 w = *(__nv_bfloat162*)&w2;
    __nv_bfloat162 r = __hmul2(w, __hsub2(a, b));
    return *(uint32_t*)&r;
}
__device__ __forceinline__ void ldsm4(uint32_t (&r)[4], uint32_t addr) {
    asm volatile("ldmatrix.sync.aligned.m8n8.x4.shared.b16 {%0,%1,%2,%3}, [%4];"
        : "=r"(r[0]), "=r"(r[1]), "=r"(r[2]), "=r"(r[3]) : "r"(addr));
}
__device__ __forceinline__ void mma_bf16(float (&d)[4], const uint32_t (&a)[4],
                                         uint32_t b0, uint32_t b1) {
    asm volatile("mma.sync.aligned.m16n8k16.row.col.f32.bf16.bf16.f32 "
        "{%0,%1,%2,%3}, {%4,%5,%6,%7}, {%8,%9}, {%0,%1,%2,%3};"
        : "+f"(d[0]), "+f"(d[1]), "+f"(d[2]), "+f"(d[3])
        : "r"(a[0]), "r"(a[1]), "r"(a[2]), "r"(a[3]), "r"(b0), "r"(b1));
}
// 64-thread pair barrier, ids 1..4 (id 0 reserved for __syncthreads!)
__device__ __forceinline__ void pair_bar(int wm) {
    asm volatile("bar.sync %0, 64;" :: "r"(wm + 1) : "memory");
}
// grid-wide barrier (all NB blocks resident; sense-reversing epoch)
__device__ __forceinline__ void grid_sync() {
    __syncthreads();
    if (threadIdx.x == 0) {
        __threadfence();
        unsigned e = atomicAdd(&g_epoch, 0u);
        if (atomicAdd(&g_ctr, 1u) == (unsigned)(gridDim.x - 1)) {
            g_ctr = 0;
            __threadfence();
            atomicExch(&g_epoch, e + 1u);
        } else {
            while (atomicAdd(&g_epoch, 0u) == e) __nanosleep(64);
        }
        __threadfence();
    }
    __syncthreads();
}

// ---------------- setup kernels ----------------
__global__ void __launch_bounds__(256) k_pz(const float* __restrict__ xn,
                                            const float* __restrict__ K1,
                                            int nN, int nPB) {
    if (blockIdx.x >= nPB) {
        int i = (blockIdx.x - nPB) * 256 + threadIdx.x;
        if (i < nN) g_deg[i] = 0.0f;
        return;
    }
    __shared__ float Ks[C * CIN];
    __shared__ float xs[CIN * 64];
    int tid = threadIdx.x;
    for (int i = tid; i < C * CIN; i += 256) Ks[i] = K1[i];
    int n0 = blockIdx.x * 64;
    for (int i = tid; i < CIN * 64; i += 256) {
        int k = i >> 6, nl = i & 63;
        int n = n0 + nl;
        xs[i] = (n < nN) ? xn[(long)k * nN + n] : 0.0f;
    }
    __syncthreads();
    int nl = tid & 63;
    int cb = (tid >> 6) * 16;
    float acc[16];
#pragma unroll
    for (int j = 0; j < 16; j++) acc[j] = 0.0f;
    for (int k = 0; k < CIN; k++) {
        float xv = xs[k * 64 + nl];
#pragma unroll
        for (int j = 0; j < 16; j++) acc[j] = fmaf(Ks[(cb + j) * CIN + k], xv, acc[j]);
    }
    int n = n0 + nl;
    if (n < nN) {
#pragma unroll
        for (int j = 0; j < 16; j++) {
            float v = fmaxf(acc[j], 0.0f);
            g_buf[0][(long)n * C + cb + j] = v;
            g_buf[1][(long)n * C + cb + j] = v;
            g_buf[2][(long)n * C + cb + j] = v;
        }
#pragma unroll
        for (int j = 0; j < 8; j++) {
            float a = fmaxf(acc[2 * j], 0.0f), b = fmaxf(acc[2 * j + 1], 0.0f);
            g_xbf[(long)n * 32 + cb / 2 + j] = bf16x2_pack(a, b);
        }
    }
}

__global__ void k_degree(const int* __restrict__ Jv, int nE) {
    int e = blockIdx.x * blockDim.x + threadIdx.x;
    if (e < nE) atomicAdd(&g_deg[Jv[e]], 1.0f);
}

__global__ void k_Wd(const int* __restrict__ Iv, const int* __restrict__ Jv, int nE) {
    int e = blockIdx.x * blockDim.x + threadIdx.x;
    if (e < nE)
        g_W[e] = rsqrtf(g_deg[Iv[e]] + 1.0f) * rsqrtf(g_deg[Jv[e]] + 1.0f);
}

// ---------------- persistent multi-layer hot kernel ----------------
// Per layer: edge phase (pair-pipelined body) -> grid_sync -> buffer
// rotation + fused init (A = 2x - x_old, bf16 mirror) -> grid_sync.
// Scatter uses shfl-bfly to form 4-contiguous channels -> RED.v4
// (halves the REDG lane-op count vs RED.v2).
__global__ void __launch_bounds__(256, 3)
k_layers(const int* __restrict__ Iv, const int* __restrict__ Jv,
         const float* __restrict__ KN2, int nE, int nN, int nLayer)
{
    extern __shared__ __align__(16) char smem[];
    __nv_bfloat16* GtA = (__nv_bfloat16*)smem;
    __nv_bfloat16* GtB = (__nv_bfloat16*)(smem + GT_BYTES);
    __nv_bfloat16* Tt  = (__nv_bfloat16*)(smem + 2 * GT_BYTES);
    __nv_bfloat16* Bs  = (__nv_bfloat16*)(smem + 3 * GT_BYTES);
    int*   sI = (int*)(smem + 3 * GT_BYTES + BS_BYTES);   // [4][TE]
    int*   sJ = sI + 4 * TE;
    float* sW = (float*)(sJ + 4 * TE);

    int tid = threadIdx.x, lane = tid & 31, wid = tid >> 5;
    int gid = lane >> 2, tig = lane & 3;
    int wm = wid & 3, wn = wid >> 2;
    int mbase = wm * 32, nbase = wn * 32;

    uint32_t gba = smem_u32(GtA), gbb = smem_u32(GtB), tb = smem_u32(Tt);
    uint32_t bsb = smem_u32(Bs);
    int lrow = (lane & 7) + ((lane >> 3) & 1) * 8;
    int lcol = ((lane >> 4) & 1) * 8;
    int bg = lane >> 3;
    uint32_t bAddr0 = bsb + (nbase + ((bg >> 1) * 8) + (lane & 7)) * (GSB * 2)
                    + (bg & 1) * 16;                     // nt pair {0,1}
    uint32_t bAddr1 = bAddr0 + 16 * (GSB * 2);           // nt pair {2,3}

    const uint32_t* xb = g_xbf;
    long stride = (long)gridDim.x * TE;
    int n4 = nN * C / 4;
    int cur = 0, old = 1, nxt = 2;

    for (int l = 0; l < nLayer; l++) {
        const float* Km = KN2 + (long)l * C * C;
        float* A = g_buf[nxt];

        // ---- Bs[n][k] = Km[n*64+k] as bf16 ----
        for (int i = tid; i < C * 32; i += 256) {
            int n = i >> 5, kq = i & 31;
            *(uint32_t*)((char*)Bs + n * (GSB * 2) + kq * 4) =
                bf16x2_pack(Km[n * 64 + 2 * kq], Km[n * 64 + 2 * kq + 1]);
        }

        long e0 = (long)blockIdx.x * TE;
        // pair-local idx loader
        auto load_idx = [&](long eb, int s) {
            if (wn == 0) {
                long e = eb + mbase + lane;
                bool ok = e < (long)nE;
                int t = s * TE + mbase + lane;
                sI[t] = ok ? Iv[e] : 0;
                sJ[t] = ok ? Jv[e] : 0;
                sW[t] = ok ? g_W[e] : 0.0f;
            }
        };

        load_idx(e0, 0);
        load_idx(e0 + stride, 1);
        __syncthreads();                // Bs + initial idx visible block-wide
        {
            int eb = mbase + wn * 16;
#pragma unroll 4
            for (int el = 0; el < 16; el++) {
                int e = eb + el;
                uint32_t w2 = bf16x2_pack(sW[e], sW[e]);
                uint32_t xi = xb[(long)sI[e] * 32 + lane];
                uint32_t xj = xb[(long)sJ[e] * 32 + lane];
                *(uint32_t*)((char*)GtA + e * (GSB * 2) + lane * 4) =
                    gdiff(xi, xj, w2);
            }
        }

        int s0 = 0;
        int curbuf = 0;
        for (; e0 < nE; e0 += stride) {
            int s1 = (s0 + 1) & 3, s2 = (s0 + 2) & 3;
            uint32_t gcur = curbuf ? gbb : gba;
            char* gnext = (char*)(curbuf ? GtA : GtB);
            pair_bar(wm);               // pair's Gt/Tt consumed, idx ready
            // ---- Phase A ----
            load_idx(e0 + 2 * stride, s2);

            float acc[2][4][4];
#pragma unroll
            for (int mt = 0; mt < 2; mt++)
#pragma unroll
                for (int nt = 0; nt < 4; nt++)
#pragma unroll
                    for (int q = 0; q < 4; q++) acc[mt][nt][q] = 0.0f;

            const int* sIc = sI + s1 * TE;
            const int* sJc = sJ + s1 * TE;
            const float* sWc = sW + s1 * TE;
            int ebg = mbase + wn * 16;
            uint32_t xiu[8], xju[8];
            // wave 0 loads (this warp's edges 0-7, tile k+1)
#pragma unroll
            for (int el = 0; el < 8; el++) {
                int e = ebg + el;
                xiu[el] = xb[(long)sIc[e] * 32 + lane];
                xju[el] = xb[(long)sJc[e] * 32 + lane];
            }
            // GEMM1 kt = 0,1
#pragma unroll
            for (int kt = 0; kt < 2; kt++) {
                uint32_t b01[4], b23[4];
                ldsm4(b01, bAddr0 + kt * 32);
                ldsm4(b23, bAddr1 + kt * 32);
#pragma unroll
                for (int mt = 0; mt < 2; mt++) {
                    uint32_t af[4];
                    ldsm4(af, gcur + (mbase + mt * 16 + lrow) * (GSB * 2)
                                  + (kt * 16 + lcol) * 2);
                    mma_bf16(acc[mt][0], af, b01[0], b01[1]);
                    mma_bf16(acc[mt][1], af, b01[2], b01[3]);
                    mma_bf16(acc[mt][2], af, b23[0], b23[1]);
                    mma_bf16(acc[mt][3], af, b23[2], b23[3]);
                }
            }
            // store wave 0
#pragma unroll
            for (int el = 0; el < 8; el++) {
                int e = ebg + el;
                uint32_t w2 = bf16x2_pack(sWc[e], sWc[e]);
                *(uint32_t*)(gnext + e * (GSB * 2) + lane * 4) =
                    gdiff(xiu[el], xju[el], w2);
            }
            // wave 1 loads (edges 8-15)
#pragma unroll
            for (int el = 0; el < 8; el++) {
                int e = ebg + 8 + el;
                xiu[el] = xb[(long)sIc[e] * 32 + lane];
                xju[el] = xb[(long)sJc[e] * 32 + lane];
            }
            // GEMM1 kt = 2,3
#pragma unroll
            for (int kt = 2; kt < 4; kt++) {
                uint32_t b01[4], b23[4];
                ldsm4(b01, bAddr0 + kt * 32);
                ldsm4(b23, bAddr1 + kt * 32);
#pragma unroll
                for (int mt = 0; mt < 2; mt++) {
                    uint32_t af[4];
                    ldsm4(af, gcur + (mbase + mt * 16 + lrow) * (GSB * 2)
                                  + (kt * 16 + lcol) * 2);
                    mma_bf16(acc[mt][0], af, b01[0], b01[1]);
                    mma_bf16(acc[mt][1], af, b01[2], b01[3]);
                    mma_bf16(acc[mt][2], af, b23[0], b23[1]);
                    mma_bf16(acc[mt][3], af, b23[2], b23[3]);
                }
            }
            // store wave 1
#pragma unroll
            for (int el = 0; el < 8; el++) {
                int e = ebg + 8 + el;
                uint32_t w2 = bf16x2_pack(sWc[e], sWc[e]);
                *(uint32_t*)(gnext + e * (GSB * 2) + lane * 4) =
                    gdiff(xiu[el], xju[el], w2);
            }
            // tanh -> Tt (pair rows, this warp's column half)
#pragma unroll
            for (int mt = 0; mt < 2; mt++) {
                int er = mbase + mt * 16 + gid;
#pragma unroll
                for (int nt = 0; nt < 4; nt++) {
                    int o = nbase + nt * 8 + tig * 2;
                    *(uint32_t*)((char*)Tt + er * (GSB * 2) + o * 2) =
                        bf16x2_pack(tanh_fast(acc[mt][nt][0]),
                                    tanh_fast(acc[mt][nt][1]));
                    *(uint32_t*)((char*)Tt + (er + 8) * (GSB * 2) + o * 2) =
                        bf16x2_pack(tanh_fast(acc[mt][nt][2]),
                                    tanh_fast(acc[mt][nt][3]));
                }
            }
            pair_bar(wm);               // Tt pair rows complete (both halves)
            // ---- Phase B: GEMM2 + scatter ----
#pragma unroll
            for (int mt = 0; mt < 2; mt++)
#pragma unroll
                for (int nt = 0; nt < 4; nt++)
#pragma unroll
                    for (int q = 0; q < 4; q++) acc[mt][nt][q] = 0.0f;
#pragma unroll
            for (int kt = 0; kt < 4; kt++) {
                uint32_t b01[4], b23[4];
                ldsm4(b01, bAddr0 + kt * 32);
                ldsm4(b23, bAddr1 + kt * 32);
#pragma unroll
                for (int mt = 0; mt < 2; mt++) {
                    uint32_t af[4];
                    ldsm4(af, tb + (mbase + mt * 16 + lrow) * (GSB * 2)
                                 + (kt * 16 + lcol) * 2);
                    mma_bf16(acc[mt][0], af, b01[0], b01[1]);
                    mma_bf16(acc[mt][1], af, b01[2], b01[3]);
                    mma_bf16(acc[mt][2], af, b23[0], b23[1]);
                    mma_bf16(acc[mt][3], af, b23[2], b23[3]);
                }
            }
            // ---- scatter: shfl-bfly pairing -> RED.v4 ----
            // Lane (gid, tig): even tig keeps row er, odd tig takes row er+8.
            // Exchange with lane^1 supplies the missing 2-of-4 channel block.
            const int* sIs = sI + s0 * TE;
            const int* sJs = sJ + s0 * TE;
            const float* sWs = sW + s0 * TE;
            int parity = tig & 1;
#pragma unroll
            for (int mt = 0; mt < 2; mt++) {
#pragma unroll
                for (int nt = 0; nt < 4; nt++) {
                    float sLo = parity ? acc[mt][nt][0] : acc[mt][nt][2];
                    float sHi = parity ? acc[mt][nt][1] : acc[mt][nt][3];
                    float rLo = __shfl_xor_sync(0xffffffffu, sLo, 1);
                    float rHi = __shfl_xor_sync(0xffffffffu, sHi, 1);
                    float v0 = parity ? rLo : acc[mt][nt][0];
                    float v1 = parity ? rHi : acc[mt][nt][1];
                    float v2 = parity ? acc[mt][nt][2] : rLo;
                    float v3 = parity ? acc[mt][nt][3] : rHi;
                    int row = mbase + mt * 16 + gid + (parity ? 8 : 0);
                    float s = H2f * sWs[row];
                    long ni = sIs[row], nj = sJs[row];
                    int cb = nbase + nt * 8 + (tig & 2) * 2;
                    float* pi = A + ni * 64 + cb;
                    float* pj = A + nj * 64 + cb;
                    asm volatile("red.global.add.v4.f32 [%0], {%1, %2, %3, %4};"
                                 :: "l"(pi), "f"(-s * v0), "f"(-s * v1),
                                    "f"(-s * v2), "f"(-s * v3) : "memory");
                    asm volatile("red.global.add.v4.f32 [%0], {%1, %2, %3, %4};"
                                 :: "l"(pj), "f"(s * v0), "f"(s * v1),
                                    "f"(s * v2), "f"(s * v3) : "memory");
                }
            }
            s0 = s1;
            curbuf ^= 1;
        }

        // ---- layer boundary ----
        grid_sync();                    // all scatters of layer l complete
        int t = old; old = cur; cur = nxt; nxt = t;
        if (l + 1 < nLayer) {
            const float4* xc = (const float4*)g_buf[cur];
            const float4* xo = (const float4*)g_buf[old];
            float4* An = (float4*)g_buf[nxt];
            uint2* mir = (uint2*)g_xbf;
            for (int i = blockIdx.x * 256 + tid; i < n4; i += gridDim.x * 256) {
                float4 a = xc[i], b = xo[i];
                An[i] = make_float4(2.0f * a.x - b.x, 2.0f * a.y - b.y,
                                    2.0f * a.z - b.z, 2.0f * a.w - b.w);
                mir[i] = make_uint2(bf16x2_pack(a.x, a.y), bf16x2_pack(a.z, a.w));
            }
            grid_sync();                // init complete before next layer
        }
    }
}

// out[n][o] = sum_c KNclose[o][c] * x[n][c]
__global__ void __launch_bounds__(128) k_out(int xIdx, const float* __restrict__ KNc,
                                             float* __restrict__ out, int nN, int nOut) {
    __shared__ float Ks[40 * C];
    for (int i = threadIdx.x; i < nOut * C; i += 128) Ks[i] = KNc[i];
    __syncthreads();
    int n = blockIdx.x * 128 + threadIdx.x;
    if (n >= nN) return;
    const float* xr = g_buf[xIdx] + (long)n * C;
    float xv[C];
#pragma unroll
    for (int q = 0; q < C / 4; q++) {
        float4 v = ((const float4*)xr)[q];
        xv[4 * q] = v.x; xv[4 * q + 1] = v.y; xv[4 * q + 2] = v.z; xv[4 * q + 3] = v.w;
    }
    for (int o = 0; o < nOut; o++) {
        float acc = 0.0f;
#pragma unroll
        for (int c = 0; c < C; c++) acc = fmaf(Ks[o * C + c], xv[c], acc);
        out[(long)n * nOut + o] = acc;
    }
}

extern "C" void kernel_launch(void* const* d_in, const int* in_sizes, int n_in,
                              void* d_out, int out_size) {
    const float* xn = (const float*)d_in[0];
    const int* Iv = (const int*)d_in[1];
    const int* Jv = (const int*)d_in[2];
    int idx = 3;
    if (n_in >= 7 && in_sizes[3] == 1) idx = 4;   // skip scalar n_nodes input
    const float* K1  = (const float*)d_in[idx];
    const float* KN2 = (const float*)d_in[idx + 1];
    const float* KNc = (const float*)d_in[idx + 2];
    int nE = in_sizes[1];
    int nN = in_sizes[0] / CIN;
    int nLayer = in_sizes[idx + 1] / (C * C);
    int nOut = in_sizes[idx + 2] / C;
    float* out = (float*)d_out;

    cudaFuncSetAttribute(k_layers, cudaFuncAttributeMaxDynamicSharedMemorySize,
                         SMEM_EDGE);

    int nPB = (nN + 63) / 64;
    int nZB = (nN + 255) / 256;
    k_pz<<<nPB + nZB, 256>>>(xn, K1, nN, nPB);
    k_degree<<<(nE + 255) / 256, 256>>>(Jv, nE);
    k_Wd<<<(nE + 255) / 256, 256>>>(Iv, Jv, nE);

    k_layers<<<NB, 256, SMEM_EDGE>>>(Iv, Jv, KN2, nE, nN, nLayer);

    // replicate in-kernel buffer rotation to find final cur
    int cur = 0, old = 1, nxt = 2;
    for (int l = 0; l < nLayer; l++) { int t = old; old = cur; cur = nxt; nxt = t; }
    k_out<<<(nN + 127) / 128, 128>>>(cur, KNc, out, nN, nOut);
}

// round 15
// speedup vs baseline: 1.3929x; 1.2603x over previous
#include <cuda_runtime.h>
#include <cuda_bf16.h>
#include <cstdint>

#define CIN 128
#define C 64
#define H2f 0.01f
#define NNODES 50000
#define NEDGES 800000
#define TE 128
#define GSB 72          // smem tile row stride in bf16 (144B)

#define GT_BYTES (TE * GSB * 2)
#define BS_BYTES (C * GSB * 2)
#define SMEM_EDGE (3 * GT_BYTES + BS_BYTES + 4 * TE * 12)
#define NB 456

__device__ float g_deg[NNODES];
__device__ float g_W[NEDGES];
__device__ float g_buf[3][(long)NNODES * C];
__device__ uint32_t g_xbf[(long)NNODES * C / 2];   // bf16 mirror of x_cur
__device__ unsigned g_ctr = 0;
__device__ unsigned g_epoch = 0;

// ---------------- helpers ----------------
__device__ __forceinline__ uint32_t smem_u32(const void* p) {
    uint32_t a;
    asm("{ .reg .u64 t; cvta.to.shared.u64 t, %1; cvt.u32.u64 %0, t; }"
        : "=r"(a) : "l"(p));
    return a;
}
__device__ __forceinline__ float tanh_fast(float x) {
    float y;
    asm("tanh.approx.f32 %0, %1;" : "=f"(y) : "f"(x));
    return y;
}
// pack bf16x2: lo = a, hi = b
__device__ __forceinline__ uint32_t bf16x2_pack(float a, float b) {
    uint32_t r;
    asm("cvt.rn.satfinite.bf16x2.f32 %0, %1, %2;" : "=r"(r) : "f"(b), "f"(a));
    return r;
}
// g = w2 * (xi - xj), all bf16x2 packed in u32
__device__ __forceinline__ uint32_t gdiff(uint32_t xi, uint32_t xj, uint32_t w2) {
    __nv_bfloat162 a = *(__nv_bfloat162*)&xi;
    __nv_bfloat162 b = *(__nv_bfloat162*)&xj;
    __nv_bfloat162 w = *(__nv_bfloat162*)&w2;
    __nv_bfloat162 r = __hmul2(w, __hsub2(a, b));
    return *(uint32_t*)&r;
}
__device__ __forceinline__ float2 bf2f2(uint32_t u) {
    __nv_bfloat162 b = *(__nv_bfloat162*)&u;
    return __bfloat1622float2(b);
}
__device__ __forceinline__ void ldsm4(uint32_t (&r)[4], uint32_t addr) {
    asm volatile("ldmatrix.sync.aligned.m8n8.x4.shared.b16 {%0,%1,%2,%3}, [%4];"
        : "=r"(r[0]), "=r"(r[1]), "=r"(r[2]), "=r"(r[3]) : "r"(addr));
}
__device__ __forceinline__ void mma_bf16(float (&d)[4], const uint32_t (&a)[4],
                                         uint32_t b0, uint32_t b1) {
    asm volatile("mma.sync.aligned.m16n8k16.row.col.f32.bf16.bf16.f32 "
        "{%0,%1,%2,%3}, {%4,%5,%6,%7}, {%8,%9}, {%0,%1,%2,%3};"
        : "+f"(d[0]), "+f"(d[1]), "+f"(d[2]), "+f"(d[3])
        : "r"(a[0]), "r"(a[1]), "r"(a[2]), "r"(a[3]), "r"(b0), "r"(b1));
}
// 64-thread pair barrier, ids 1..4 (id 0 reserved for __syncthreads!)
__device__ __forceinline__ void pair_bar(int wm) {
    asm volatile("bar.sync %0, 64;" :: "r"(wm + 1) : "memory");
}
// grid-wide barrier (all NB blocks resident; sense-reversing epoch)
__device__ __forceinline__ void grid_sync() {
    __syncthreads();
    if (threadIdx.x == 0) {
        __threadfence();
        unsigned e = atomicAdd(&g_epoch, 0u);
        if (atomicAdd(&g_ctr, 1u) == (unsigned)(gridDim.x - 1)) {
            g_ctr = 0;
            __threadfence();
            atomicExch(&g_epoch, e + 1u);
        } else {
            while (atomicAdd(&g_epoch, 0u) == e) __nanosleep(64);
        }
        __threadfence();
    }
    __syncthreads();
}

// ---------------- setup kernels ----------------
__global__ void __launch_bounds__(256) k_pz(const float* __restrict__ xn,
                                            const float* __restrict__ K1,
                                            int nN, int nPB) {
    if (blockIdx.x >= nPB) {
        int i = (blockIdx.x - nPB) * 256 + threadIdx.x;
        if (i < nN) g_deg[i] = 0.0f;
        return;
    }
    __shared__ float Ks[C * CIN];
    __shared__ float xs[CIN * 64];
    int tid = threadIdx.x;
    for (int i = tid; i < C * CIN; i += 256) Ks[i] = K1[i];
    int n0 = blockIdx.x * 64;
    for (int i = tid; i < CIN * 64; i += 256) {
        int k = i >> 6, nl = i & 63;
        int n = n0 + nl;
        xs[i] = (n < nN) ? xn[(long)k * nN + n] : 0.0f;
    }
    __syncthreads();
    int nl = tid & 63;
    int cb = (tid >> 6) * 16;
    float acc[16];
#pragma unroll
    for (int j = 0; j < 16; j++) acc[j] = 0.0f;
    for (int k = 0; k < CIN; k++) {
        float xv = xs[k * 64 + nl];
#pragma unroll
        for (int j = 0; j < 16; j++) acc[j] = fmaf(Ks[(cb + j) * CIN + k], xv, acc[j]);
    }
    int n = n0 + nl;
    if (n < nN) {
#pragma unroll
        for (int j = 0; j < 16; j++) {
            float v = fmaxf(acc[j], 0.0f);
            g_buf[0][(long)n * C + cb + j] = v;
            g_buf[1][(long)n * C + cb + j] = v;
            g_buf[2][(long)n * C + cb + j] = v;
        }
#pragma unroll
        for (int j = 0; j < 8; j++) {
            float a = fmaxf(acc[2 * j], 0.0f), b = fmaxf(acc[2 * j + 1], 0.0f);
            g_xbf[(long)n * 32 + cb / 2 + j] = bf16x2_pack(a, b);
        }
    }
}

__global__ void k_degree(const int* __restrict__ Jv, int nE) {
    int e = blockIdx.x * blockDim.x + threadIdx.x;
    if (e < nE) atomicAdd(&g_deg[Jv[e]], 1.0f);
}

__global__ void k_Wd(const int* __restrict__ Iv, const int* __restrict__ Jv, int nE) {
    int e = blockIdx.x * blockDim.x + threadIdx.x;
    if (e < nE)
        g_W[e] = rsqrtf(g_deg[Iv[e]] + 1.0f) * rsqrtf(g_deg[Jv[e]] + 1.0f);
}

// ---------------- persistent multi-layer hot kernel ----------------
// Per layer: edge phase (pair-pipelined body) -> grid_sync -> buffer
// rotation + fused init -> grid_sync. Scatter: d staged bf16 edge-major into
// the consumed gcur buffer, then per-edge coalesced RED.v4 (lanes 0-15 -> I
// row, 16-31 -> J row; 4 lines/instr instead of ~32).
__global__ void __launch_bounds__(256, 3)
k_layers(const int* __restrict__ Iv, const int* __restrict__ Jv,
         const float* __restrict__ KN2, int nE, int nN, int nLayer)
{
    extern __shared__ __align__(16) char smem[];
    __nv_bfloat16* GtA = (__nv_bfloat16*)smem;
    __nv_bfloat16* GtB = (__nv_bfloat16*)(smem + GT_BYTES);
    __nv_bfloat16* Tt  = (__nv_bfloat16*)(smem + 2 * GT_BYTES);
    __nv_bfloat16* Bs  = (__nv_bfloat16*)(smem + 3 * GT_BYTES);
    int*   sI = (int*)(smem + 3 * GT_BYTES + BS_BYTES);   // [4][TE]
    int*   sJ = sI + 4 * TE;
    float* sW = (float*)(sJ + 4 * TE);

    int tid = threadIdx.x, lane = tid & 31, wid = tid >> 5;
    int gid = lane >> 2, tig = lane & 3;
    int wm = wid & 3, wn = wid >> 2;
    int mbase = wm * 32, nbase = wn * 32;
    int lh = lane & 15;

    uint32_t gba = smem_u32(GtA), gbb = smem_u32(GtB), tb = smem_u32(Tt);
    uint32_t bsb = smem_u32(Bs);
    int lrow = (lane & 7) + ((lane >> 3) & 1) * 8;
    int lcol = ((lane >> 4) & 1) * 8;
    int bg = lane >> 3;
    uint32_t bAddr0 = bsb + (nbase + ((bg >> 1) * 8) + (lane & 7)) * (GSB * 2)
                    + (bg & 1) * 16;                     // nt pair {0,1}
    uint32_t bAddr1 = bAddr0 + 16 * (GSB * 2);           // nt pair {2,3}

    const uint32_t* xb = g_xbf;
    long stride = (long)gridDim.x * TE;
    int n4 = nN * C / 4;
    int cur = 0, old = 1, nxt = 2;

    for (int l = 0; l < nLayer; l++) {
        const float* Km = KN2 + (long)l * C * C;
        float* A = g_buf[nxt];

        // ---- Bs[n][k] = Km[n*64+k] as bf16 ----
        for (int i = tid; i < C * 32; i += 256) {
            int n = i >> 5, kq = i & 31;
            *(uint32_t*)((char*)Bs + n * (GSB * 2) + kq * 4) =
                bf16x2_pack(Km[n * 64 + 2 * kq], Km[n * 64 + 2 * kq + 1]);
        }

        long e0 = (long)blockIdx.x * TE;
        // pair-local idx loader
        auto load_idx = [&](long eb, int s) {
            if (wn == 0) {
                long e = eb + mbase + lane;
                bool ok = e < (long)nE;
                int t = s * TE + mbase + lane;
                sI[t] = ok ? Iv[e] : 0;
                sJ[t] = ok ? Jv[e] : 0;
                sW[t] = ok ? g_W[e] : 0.0f;
            }
        };

        load_idx(e0, 0);
        load_idx(e0 + stride, 1);
        __syncthreads();                // Bs + initial idx visible block-wide
        {
            int eb = mbase + wn * 16;
#pragma unroll 4
            for (int el = 0; el < 16; el++) {
                int e = eb + el;
                uint32_t w2 = bf16x2_pack(sW[e], sW[e]);
                uint32_t xi = xb[(long)sI[e] * 32 + lane];
                uint32_t xj = xb[(long)sJ[e] * 32 + lane];
                *(uint32_t*)((char*)GtA + e * (GSB * 2) + lane * 4) =
                    gdiff(xi, xj, w2);
            }
        }

        int s0 = 0;
        int curbuf = 0;
        for (; e0 < nE; e0 += stride) {
            int s1 = (s0 + 1) & 3, s2 = (s0 + 2) & 3;
            uint32_t gcur = curbuf ? gbb : gba;
            char* gcurp = (char*)(curbuf ? GtB : GtA);
            char* gnext = (char*)(curbuf ? GtA : GtB);
            pair_bar(wm);               // pair's Gt/Tt consumed, idx ready
            // ---- Phase A ----
            load_idx(e0 + 2 * stride, s2);

            float acc[2][4][4];
#pragma unroll
            for (int mt = 0; mt < 2; mt++)
#pragma unroll
                for (int nt = 0; nt < 4; nt++)
#pragma unroll
                    for (int q = 0; q < 4; q++) acc[mt][nt][q] = 0.0f;

            const int* sIc = sI + s1 * TE;
            const int* sJc = sJ + s1 * TE;
            const float* sWc = sW + s1 * TE;
            int ebg = mbase + wn * 16;
            uint32_t xiu[8], xju[8];
            // wave 0 loads (this warp's edges 0-7, tile k+1)
#pragma unroll
            for (int el = 0; el < 8; el++) {
                int e = ebg + el;
                xiu[el] = xb[(long)sIc[e] * 32 + lane];
                xju[el] = xb[(long)sJc[e] * 32 + lane];
            }
            // GEMM1 kt = 0,1
#pragma unroll
            for (int kt = 0; kt < 2; kt++) {
                uint32_t b01[4], b23[4];
                ldsm4(b01, bAddr0 + kt * 32);
                ldsm4(b23, bAddr1 + kt * 32);
#pragma unroll
                for (int mt = 0; mt < 2; mt++) {
                    uint32_t af[4];
                    ldsm4(af, gcur + (mbase + mt * 16 + lrow) * (GSB * 2)
                                  + (kt * 16 + lcol) * 2);
                    mma_bf16(acc[mt][0], af, b01[0], b01[1]);
                    mma_bf16(acc[mt][1], af, b01[2], b01[3]);
                    mma_bf16(acc[mt][2], af, b23[0], b23[1]);
                    mma_bf16(acc[mt][3], af, b23[2], b23[3]);
                }
            }
            // store wave 0
#pragma unroll
            for (int el = 0; el < 8; el++) {
                int e = ebg + el;
                uint32_t w2 = bf16x2_pack(sWc[e], sWc[e]);
                *(uint32_t*)(gnext + e * (GSB * 2) + lane * 4) =
                    gdiff(xiu[el], xju[el], w2);
            }
            // wave 1 loads (edges 8-15)
#pragma unroll
            for (int el = 0; el < 8; el++) {
                int e = ebg + 8 + el;
                xiu[el] = xb[(long)sIc[e] * 32 + lane];
                xju[el] = xb[(long)sJc[e] * 32 + lane];
            }
            // GEMM1 kt = 2,3
#pragma unroll
            for (int kt = 2; kt < 4; kt++) {
                uint32_t b01[4], b23[4];
                ldsm4(b01, bAddr0 + kt * 32);
                ldsm4(b23, bAddr1 + kt * 32);
#pragma unroll
                for (int mt = 0; mt < 2; mt++) {
                    uint32_t af[4];
                    ldsm4(af, gcur + (mbase + mt * 16 + lrow) * (GSB * 2)
                                  + (kt * 16 + lcol) * 2);
                    mma_bf16(acc[mt][0], af, b01[0], b01[1]);
                    mma_bf16(acc[mt][1], af, b01[2], b01[3]);
                    mma_bf16(acc[mt][2], af, b23[0], b23[1]);
                    mma_bf16(acc[mt][3], af, b23[2], b23[3]);
                }
            }
            // store wave 1
#pragma unroll
            for (int el = 0; el < 8; el++) {
                int e = ebg + 8 + el;
                uint32_t w2 = bf16x2_pack(sWc[e], sWc[e]);
                *(uint32_t*)(gnext + e * (GSB * 2) + lane * 4) =
                    gdiff(xiu[el], xju[el], w2);
            }
            // tanh -> Tt (pair rows, this warp's column half)
#pragma unroll
            for (int mt = 0; mt < 2; mt++) {
                int er = mbase + mt * 16 + gid;
#pragma unroll
                for (int nt = 0; nt < 4; nt++) {
                    int o = nbase + nt * 8 + tig * 2;
                    *(uint32_t*)((char*)Tt + er * (GSB * 2) + o * 2) =
                        bf16x2_pack(tanh_fast(acc[mt][nt][0]),
                                    tanh_fast(acc[mt][nt][1]));
                    *(uint32_t*)((char*)Tt + (er + 8) * (GSB * 2) + o * 2) =
                        bf16x2_pack(tanh_fast(acc[mt][nt][2]),
                                    tanh_fast(acc[mt][nt][3]));
                }
            }
            pair_bar(wm);               // Tt pair rows complete (both halves)
            // ---- Phase B: GEMM2 ----
#pragma unroll
            for (int mt = 0; mt < 2; mt++)
#pragma unroll
                for (int nt = 0; nt < 4; nt++)
#pragma unroll
                    for (int q = 0; q < 4; q++) acc[mt][nt][q] = 0.0f;
#pragma unroll
            for (int kt = 0; kt < 4; kt++) {
                uint32_t b01[4], b23[4];
                ldsm4(b01, bAddr0 + kt * 32);
                ldsm4(b23, bAddr1 + kt * 32);
#pragma unroll
                for (int mt = 0; mt < 2; mt++) {
                    uint32_t af[4];
                    ldsm4(af, tb + (mbase + mt * 16 + lrow) * (GSB * 2)
                                 + (kt * 16 + lcol) * 2);
                    mma_bf16(acc[mt][0], af, b01[0], b01[1]);
                    mma_bf16(acc[mt][1], af, b01[2], b01[3]);
                    mma_bf16(acc[mt][2], af, b23[0], b23[1]);
                    mma_bf16(acc[mt][3], af, b23[2], b23[3]);
                }
            }
            // ---- stage d (bf16) edge-major into consumed gcur buffer ----
#pragma unroll
            for (int mt = 0; mt < 2; mt++) {
                int er = mbase + mt * 16 + gid;
#pragma unroll
                for (int nt = 0; nt < 4; nt++) {
                    int o = nbase + nt * 8 + tig * 2;
                    *(uint32_t*)(gcurp + er * (GSB * 2) + o * 2) =
                        bf16x2_pack(acc[mt][nt][0], acc[mt][nt][1]);
                    *(uint32_t*)(gcurp + (er + 8) * (GSB * 2) + o * 2) =
                        bf16x2_pack(acc[mt][nt][2], acc[mt][nt][3]);
                }
            }
            pair_bar(wm);               // both column halves staged
            // ---- coalesced scatter: lanes 0-15 -> I (neg), 16-31 -> J ----
            {
                const int* sIs = sI + s0 * TE;
                const int* sJs = sJ + s0 * TE;
                const float* sWs = sW + s0 * TE;
#pragma unroll 4
                for (int el = 0; el < 16; el++) {
                    int e = ebg + el;
                    uint2 dpk = *(uint2*)(gcurp + e * (GSB * 2) + lh * 8);
                    float2 dlo = bf2f2(dpk.x);
                    float2 dhi = bf2f2(dpk.y);
                    float s = H2f * sWs[e];
                    if (lane < 16) s = -s;
                    long node = (lane < 16) ? sIs[e] : sJs[e];
                    float* p4 = A + node * 64 + 4 * lh;
                    asm volatile("red.global.add.v4.f32 [%0], {%1, %2, %3, %4};"
                                 :: "l"(p4), "f"(s * dlo.x), "f"(s * dlo.y),
                                    "f"(s * dhi.x), "f"(s * dhi.y) : "memory");
                }
            }
            s0 = s1;
            curbuf ^= 1;
        }

        // ---- layer boundary ----
        grid_sync();                    // all scatters of layer l complete
        int t = old; old = cur; cur = nxt; nxt = t;
        if (l + 1 < nLayer) {
            const float4* xc = (const float4*)g_buf[cur];
            const float4* xo = (const float4*)g_buf[old];
            float4* An = (float4*)g_buf[nxt];
            uint2* mir = (uint2*)g_xbf;
            for (int i = blockIdx.x * 256 + tid; i < n4; i += gridDim.x * 256) {
                float4 a = xc[i], b = xo[i];
                An[i] = make_float4(2.0f * a.x - b.x, 2.0f * a.y - b.y,
                                    2.0f * a.z - b.z, 2.0f * a.w - b.w);
                mir[i] = make_uint2(bf16x2_pack(a.x, a.y), bf16x2_pack(a.z, a.w));
            }
            grid_sync();                // init complete before next layer
        }
    }
}

// out[n][o] = sum_c KNclose[o][c] * x[n][c]
__global__ void __launch_bounds__(128) k_out(int xIdx, const float* __restrict__ KNc,
                                             float* __restrict__ out, int nN, int nOut) {
    __shared__ float Ks[40 * C];
    for (int i = threadIdx.x; i < nOut * C; i += 128) Ks[i] = KNc[i];
    __syncthreads();
    int n = blockIdx.x * 128 + threadIdx.x;
    if (n >= nN) return;
    const float* xr = g_buf[xIdx] + (long)n * C;
    float xv[C];
#pragma unroll
    for (int q = 0; q < C / 4; q++) {
        float4 v = ((const float4*)xr)[q];
        xv[4 * q] = v.x; xv[4 * q + 1] = v.y; xv[4 * q + 2] = v.z; xv[4 * q + 3] = v.w;
    }
    for (int o = 0; o < nOut; o++) {
        float acc = 0.0f;
#pragma unroll
        for (int c = 0; c < C; c++) acc = fmaf(Ks[o * C + c], xv[c], acc);
        out[(long)n * nOut + o] = acc;
    }
}

extern "C" void kernel_launch(void* const* d_in, const int* in_sizes, int n_in,
                              void* d_out, int out_size) {
    const float* xn = (const float*)d_in[0];
    const int* Iv = (const int*)d_in[1];
    const int* Jv = (const int*)d_in[2];
    int idx = 3;
    if (n_in >= 7 && in_sizes[3] == 1) idx = 4;   // skip scalar n_nodes input
    const float* K1  = (const float*)d_in[idx];
    const float* KN2 = (const float*)d_in[idx + 1];
    const float* KNc = (const float*)d_in[idx + 2];
    int nE = in_sizes[1];
    int nN = in_sizes[0] / CIN;
    int nLayer = in_sizes[idx + 1] / (C * C);
    int nOut = in_sizes[idx + 2] / C;
    float* out = (float*)d_out;

    cudaFuncSetAttribute(k_layers, cudaFuncAttributeMaxDynamicSharedMemorySize,
                         SMEM_EDGE);

    int nPB = (nN + 63) / 64;
    int nZB = (nN + 255) / 256;
    k_pz<<<nPB + nZB, 256>>>(xn, K1, nN, nPB);
    k_degree<<<(nE + 255) / 256, 256>>>(Jv, nE);
    k_Wd<<<(nE + 255) / 256, 256>>>(Iv, Jv, nE);

    k_layers<<<NB, 256, SMEM_EDGE>>>(Iv, Jv, KN2, nE, nN, nLayer);

    // replicate in-kernel buffer rotation to find final cur
    int cur = 0, old = 1, nxt = 2;
    for (int l = 0; l < nLayer; l++) { int t = old; old = cur; cur = nxt; nxt = t; }
    k_out<<<(nN + 127) / 128, 128>>>(cur, KNc, out, nN, nOut);
}

// round 16
// speedup vs baseline: 1.4125x; 1.0141x over previous
#include <cuda_runtime.h>
#include <cuda_bf16.h>
#include <cstdint>

#define CIN 128
#define C 64
#define H2f 0.01f
#define NNODES 50000
#define NEDGES 800000
#define GSB 72            // smem row stride in bf16 (144B)
#define GSB2 144
#define WTILE 16          // edges per warp-iter
#define TILE_B (WTILE * GSB2)       // 2304 B per G tile
#define PSTRIDE (16 * GSB2)         // B nt-pair stride

// smem map: [0,36864) 8 warps x 2 G tiles; [36864,46080) Bs; then idx rings
#define OFF_BS   36864
#define OFF_SI   46080
#define OFF_SJ   48128
#define OFF_SW   50176
#define SMEM_EDGE 52224
#define NB 304            // 2 CTAs/SM x 152 — ALL resident (grid barrier safe)

__device__ float g_deg[NNODES];
__device__ float g_W[NEDGES];
__device__ float g_buf[3][(long)NNODES * C];
__device__ uint32_t g_xbf[(long)NNODES * C / 2];   // bf16 mirror of x_cur
__device__ unsigned g_ctr = 0;
__device__ unsigned g_epoch = 0;

// ---------------- helpers ----------------
__device__ __forceinline__ uint32_t smem_u32(const void* p) {
    uint32_t a;
    asm("{ .reg .u64 t; cvta.to.shared.u64 t, %1; cvt.u32.u64 %0, t; }"
        : "=r"(a) : "l"(p));
    return a;
}
__device__ __forceinline__ float tanh_fast(float x) {
    float y;
    asm("tanh.approx.f32 %0, %1;" : "=f"(y) : "f"(x));
    return y;
}
__device__ __forceinline__ uint32_t bf16x2_pack(float a, float b) {
    uint32_t r;
    asm("cvt.rn.satfinite.bf16x2.f32 %0, %1, %2;" : "=r"(r) : "f"(b), "f"(a));
    return r;
}
__device__ __forceinline__ uint32_t gdiff(uint32_t xi, uint32_t xj, uint32_t w2) {
    __nv_bfloat162 a = *(__nv_bfloat162*)&xi;
    __nv_bfloat162 b = *(__nv_bfloat162*)&xj;
    __nv_bfloat162 w = *(__nv_bfloat162*)&w2;
    __nv_bfloat162 r = __hmul2(w, __hsub2(a, b));
    return *(uint32_t*)&r;
}
__device__ __forceinline__ float2 bf2f2(uint32_t u) {
    __nv_bfloat162 b = *(__nv_bfloat162*)&u;
    return __bfloat1622float2(b);
}
__device__ __forceinline__ void ldsm4(uint32_t (&r)[4], uint32_t addr) {
    asm volatile("ldmatrix.sync.aligned.m8n8.x4.shared.b16 {%0,%1,%2,%3}, [%4];"
        : "=r"(r[0]), "=r"(r[1]), "=r"(r[2]), "=r"(r[3]) : "r"(addr));
}
__device__ __forceinline__ void mma_bf16(float (&d)[4], const uint32_t (&a)[4],
                                         uint32_t b0, uint32_t b1) {
    asm volatile("mma.sync.aligned.m16n8k16.row.col.f32.bf16.bf16.f32 "
        "{%0,%1,%2,%3}, {%4,%5,%6,%7}, {%8,%9}, {%0,%1,%2,%3};"
        : "+f"(d[0]), "+f"(d[1]), "+f"(d[2]), "+f"(d[3])
        : "r"(a[0]), "r"(a[1]), "r"(a[2]), "r"(a[3]), "r"(b0), "r"(b1));
}
// grid-wide barrier (all NB blocks resident; sense-reversing epoch)
__device__ __forceinline__ void grid_sync() {
    __syncthreads();
    if (threadIdx.x == 0) {
        __threadfence();
        unsigned e = atomicAdd(&g_epoch, 0u);
        if (atomicAdd(&g_ctr, 1u) == (unsigned)(gridDim.x - 1)) {
            g_ctr = 0;
            __threadfence();
            atomicExch(&g_epoch, e + 1u);
        } else {
            while (atomicAdd(&g_epoch, 0u) == e) __nanosleep(64);
        }
        __threadfence();
    }
    __syncthreads();
}

// ---------------- setup kernels ----------------
__global__ void __launch_bounds__(256) k_pz(const float* __restrict__ xn,
                                            const float* __restrict__ K1,
                                            int nN, int nPB) {
    if (blockIdx.x >= nPB) {
        int i = (blockIdx.x - nPB) * 256 + threadIdx.x;
        if (i < nN) g_deg[i] = 0.0f;
        return;
    }
    __shared__ float Ks[C * CIN];
    __shared__ float xs[CIN * 64];
    int tid = threadIdx.x;
    for (int i = tid; i < C * CIN; i += 256) Ks[i] = K1[i];
    int n0 = blockIdx.x * 64;
    for (int i = tid; i < CIN * 64; i += 256) {
        int k = i >> 6, nl = i & 63;
        int n = n0 + nl;
        xs[i] = (n < nN) ? xn[(long)k * nN + n] : 0.0f;
    }
    __syncthreads();
    int nl = tid & 63;
    int cb = (tid >> 6) * 16;
    float acc[16];
#pragma unroll
    for (int j = 0; j < 16; j++) acc[j] = 0.0f;
    for (int k = 0; k < CIN; k++) {
        float xv = xs[k * 64 + nl];
#pragma unroll
        for (int j = 0; j < 16; j++) acc[j] = fmaf(Ks[(cb + j) * CIN + k], xv, acc[j]);
    }
    int n = n0 + nl;
    if (n < nN) {
#pragma unroll
        for (int j = 0; j < 16; j++) {
            float v = fmaxf(acc[j], 0.0f);
            g_buf[0][(long)n * C + cb + j] = v;
            g_buf[1][(long)n * C + cb + j] = v;
            g_buf[2][(long)n * C + cb + j] = v;
        }
#pragma unroll
        for (int j = 0; j < 8; j++) {
            float a = fmaxf(acc[2 * j], 0.0f), b = fmaxf(acc[2 * j + 1], 0.0f);
            g_xbf[(long)n * 32 + cb / 2 + j] = bf16x2_pack(a, b);
        }
    }
}

__global__ void k_degree(const int* __restrict__ Jv, int nE) {
    int e = blockIdx.x * blockDim.x + threadIdx.x;
    if (e < nE) atomicAdd(&g_deg[Jv[e]], 1.0f);
}

__global__ void k_Wd(const int* __restrict__ Iv, const int* __restrict__ Jv, int nE) {
    int e = blockIdx.x * blockDim.x + threadIdx.x;
    if (e < nE)
        g_W[e] = rsqrtf(g_deg[Iv[e]] + 1.0f) * rsqrtf(g_deg[Jv[e]] + 1.0f);
}

// ---------------- persistent multi-layer hot kernel ----------------
// Warp-autonomous: each warp runs an independent 16-edge pipeline with NO
// barriers in the steady loop (only __syncwarp). GEMM1 A from warp-private
// smem G; T = tanh(D1) stays IN REGISTERS and feeds GEMM2 directly (C-frag ==
// A-frag identity). d staged bf16 in consumed G buffer -> coalesced RED.v4.
// Per layer boundary: grid_sync -> rotate + fused init -> grid_sync.
// Tail: fused k_out.
__global__ void __launch_bounds__(256, 2)
k_layers(const int* __restrict__ Iv, const int* __restrict__ Jv,
         const float* __restrict__ KN2, const float* __restrict__ KNc,
         float* __restrict__ out, int nE, int nN, int nLayer, int nOut)
{
    extern __shared__ __align__(16) char smem[];
    int tid = threadIdx.x, lane = tid & 31, wid = tid >> 5;
    int gid = lane >> 2, tig = lane & 3;
    int lh = lane & 15;

    char* Gw = smem + wid * (2 * TILE_B);              // 2 private G tiles
    __nv_bfloat16* Bs = (__nv_bfloat16*)(smem + OFF_BS);
    int*   sIw = (int*)(smem + OFF_SI) + wid * 64;     // [4][16]
    int*   sJw = (int*)(smem + OFF_SJ) + wid * 64;
    float* sWw = (float*)(smem + OFF_SW) + wid * 64;

    uint32_t gw0 = smem_u32(Gw);
    uint32_t bsb = smem_u32(Bs);
    int lrow = (lane & 7) + ((lane >> 3) & 1) * 8;
    int lcol = ((lane >> 4) & 1) * 8;
    int bg = lane >> 3;
    uint32_t bBase = bsb + (((bg >> 1) * 8) + (lane & 7)) * GSB2 + (bg & 1) * 16;

    const uint32_t* xb = g_xbf;
    long stride = (long)gridDim.x * 8 * WTILE;
    int n4 = nN * C / 4;
    int cur = 0, old = 1, nxt = 2;

    for (int l = 0; l < nLayer; l++) {
        const float* Km = KN2 + (long)l * C * C;
        float* A = g_buf[nxt];

        // ---- Bs[n][k] = Km[n*64+k] as bf16 (block-shared) ----
        for (int i = tid; i < C * 32; i += 256) {
            int n = i >> 5, kq = i & 31;
            *(uint32_t*)((char*)Bs + n * GSB2 + kq * 4) =
                bf16x2_pack(Km[n * 64 + 2 * kq], Km[n * 64 + 2 * kq + 1]);
        }
        __syncthreads();

        long e0 = ((long)blockIdx.x * 8 + wid) * WTILE;
        // warp-private idx loader: lanes 0-15 -> I,W ; 16-31 -> J
        auto load_idx = [&](long eb, int s) {
            long e = eb + lh;
            bool ok = e < (long)nE;
            if (lane < 16) {
                sIw[s * 16 + lh] = ok ? Iv[e] : 0;
                sWw[s * 16 + lh] = ok ? g_W[e] : 0.0f;
            } else {
                sJw[s * 16 + lh] = ok ? Jv[e] : 0;
            }
        };

        load_idx(e0, 0);
        load_idx(e0 + stride, 1);
        __syncwarp();
        // ---- prologue gather: tile 0 -> buf 0 ----
#pragma unroll 4
        for (int el = 0; el < WTILE; el++) {
            float w = sWw[el];
            uint32_t w2 = bf16x2_pack(w, w);
            uint32_t xi = xb[(long)sIw[el] * 32 + lane];
            uint32_t xj = xb[(long)sJw[el] * 32 + lane];
            *(uint32_t*)(Gw + el * GSB2 + lane * 4) = gdiff(xi, xj, w2);
        }

        int s0 = 0, curbuf = 0;
        for (; e0 < nE; e0 += stride) {
            __syncwarp();               // gather stores -> ldsm, idx visible
            uint32_t gcur_a = gw0 + curbuf * TILE_B;
            char* gcur = Gw + curbuf * TILE_B;
            char* gnext = Gw + (curbuf ^ 1) * TILE_B;
            load_idx(e0 + 2 * stride, (s0 + 2) & 3);

            int s1 = (s0 + 1) & 3;
            const int* sIc = sIw + s1 * 16;
            const int* sJc = sJw + s1 * 16;
            const float* sWc = sWw + s1 * 16;

            float acc[8][4];
#pragma unroll
            for (int nt = 0; nt < 8; nt++)
#pragma unroll
                for (int q = 0; q < 4; q++) acc[nt][q] = 0.0f;

            uint32_t xiu[8], xju[8];
            // wave 0 loads (next tile's edges 0-7)
#pragma unroll
            for (int el = 0; el < 8; el++) {
                xiu[el] = xb[(long)sIc[el] * 32 + lane];
                xju[el] = xb[(long)sJc[el] * 32 + lane];
            }
            // GEMM1 kt = 0,1
#pragma unroll
            for (int kt = 0; kt < 2; kt++) {
                uint32_t af[4];
                ldsm4(af, gcur_a + lrow * GSB2 + (kt * 16 + lcol) * 2);
#pragma unroll
                for (int p = 0; p < 4; p++) {
                    uint32_t bf[4];
                    ldsm4(bf, bBase + p * PSTRIDE + kt * 32);
                    mma_bf16(acc[2 * p], af, bf[0], bf[1]);
                    mma_bf16(acc[2 * p + 1], af, bf[2], bf[3]);
                }
            }
            // store wave 0
#pragma unroll
            for (int el = 0; el < 8; el++) {
                float w = sWc[el];
                uint32_t w2 = bf16x2_pack(w, w);
                *(uint32_t*)(gnext + el * GSB2 + lane * 4) =
                    gdiff(xiu[el], xju[el], w2);
            }
            // wave 1 loads (edges 8-15)
#pragma unroll
            for (int el = 0; el < 8; el++) {
                xiu[el] = xb[(long)sIc[el + 8] * 32 + lane];
                xju[el] = xb[(long)sJc[el + 8] * 32 + lane];
            }
            // GEMM1 kt = 2,3
#pragma unroll
            for (int kt = 2; kt < 4; kt++) {
                uint32_t af[4];
                ldsm4(af, gcur_a + lrow * GSB2 + (kt * 16 + lcol) * 2);
#pragma unroll
                for (int p = 0; p < 4; p++) {
                    uint32_t bf[4];
                    ldsm4(bf, bBase + p * PSTRIDE + kt * 32);
                    mma_bf16(acc[2 * p], af, bf[0], bf[1]);
                    mma_bf16(acc[2 * p + 1], af, bf[2], bf[3]);
                }
            }
            // store wave 1
#pragma unroll
            for (int el = 0; el < 8; el++) {
                float w = sWc[el + 8];
                uint32_t w2 = bf16x2_pack(w, w);
                *(uint32_t*)(gnext + (el + 8) * GSB2 + lane * 4) =
                    gdiff(xiu[el], xju[el], w2);
            }
            // ---- tanh -> T, in registers (C-frag -> A-frag identity) ----
            uint32_t t[4][4];
#pragma unroll
            for (int kt = 0; kt < 4; kt++) {
                t[kt][0] = bf16x2_pack(tanh_fast(acc[2 * kt][0]),
                                       tanh_fast(acc[2 * kt][1]));
                t[kt][1] = bf16x2_pack(tanh_fast(acc[2 * kt][2]),
                                       tanh_fast(acc[2 * kt][3]));
                t[kt][2] = bf16x2_pack(tanh_fast(acc[2 * kt + 1][0]),
                                       tanh_fast(acc[2 * kt + 1][1]));
                t[kt][3] = bf16x2_pack(tanh_fast(acc[2 * kt + 1][2]),
                                       tanh_fast(acc[2 * kt + 1][3]));
            }
            // ---- GEMM2: D2 = T * B (A from registers) ----
#pragma unroll
            for (int nt = 0; nt < 8; nt++)
#pragma unroll
                for (int q = 0; q < 4; q++) acc[nt][q] = 0.0f;
#pragma unroll
            for (int kt = 0; kt < 4; kt++) {
#pragma unroll
                for (int p = 0; p < 4; p++) {
                    uint32_t bf[4];
                    ldsm4(bf, bBase + p * PSTRIDE + kt * 32);
                    mma_bf16(acc[2 * p], t[kt], bf[0], bf[1]);
                    mma_bf16(acc[2 * p + 1], t[kt], bf[2], bf[3]);
                }
            }
            // ---- stage d (bf16) edge-major into consumed gcur ----
#pragma unroll
            for (int nt = 0; nt < 8; nt++) {
                int o = nt * 8 + tig * 2;
                *(uint32_t*)(gcur + gid * GSB2 + o * 2) =
                    bf16x2_pack(acc[nt][0], acc[nt][1]);
                *(uint32_t*)(gcur + (gid + 8) * GSB2 + o * 2) =
                    bf16x2_pack(acc[nt][2], acc[nt][3]);
            }
            __syncwarp();
            // ---- coalesced scatter: lanes 0-15 -> I (neg), 16-31 -> J ----
            {
                const int* sIs = sIw + s0 * 16;
                const int* sJs = sJw + s0 * 16;
                const float* sWs = sWw + s0 * 16;
#pragma unroll 4
                for (int el = 0; el < WTILE; el++) {
                    uint2 dpk = *(uint2*)(gcur + el * GSB2 + lh * 8);
                    float2 dlo = bf2f2(dpk.x);
                    float2 dhi = bf2f2(dpk.y);
                    float s = H2f * sWs[el];
                    if (lane < 16) s = -s;
                    long node = (lane < 16) ? sIs[el] : sJs[el];
                    float* p4 = A + node * 64 + 4 * lh;
                    asm volatile("red.global.add.v4.f32 [%0], {%1, %2, %3, %4};"
                                 :: "l"(p4), "f"(s * dlo.x), "f"(s * dlo.y),
                                    "f"(s * dhi.x), "f"(s * dhi.y) : "memory");
                }
            }
            s0 = s1;
            curbuf ^= 1;
        }

        // ---- layer boundary ----
        grid_sync();                    // all scatters of layer l complete
        int tsw = old; old = cur; cur = nxt; nxt = tsw;
        if (l + 1 < nLayer) {
            const float4* xc = (const float4*)g_buf[cur];
            const float4* xo = (const float4*)g_buf[old];
            float4* An = (float4*)g_buf[nxt];
            uint2* mir = (uint2*)g_xbf;
            for (int i = blockIdx.x * 256 + tid; i < n4; i += gridDim.x * 256) {
                float4 a = xc[i], b = xo[i];
                An[i] = make_float4(2.0f * a.x - b.x, 2.0f * a.y - b.y,
                                    2.0f * a.z - b.z, 2.0f * a.w - b.w);
                mir[i] = make_uint2(bf16x2_pack(a.x, a.y), bf16x2_pack(a.z, a.w));
            }
        }
        grid_sync();                    // init done / all done with smem phase
    }

    // ---- fused output: out[n][o] = sum_c KNc[o][c] * x[n][c] ----
    {
        float* Ks = (float*)smem;       // G region free after final grid_sync
        for (int i = tid; i < nOut * C; i += 256) Ks[i] = KNc[i];
        __syncthreads();
        const float* X = g_buf[cur];
        for (int n = blockIdx.x * 256 + tid; n < nN; n += gridDim.x * 256) {
            const float* xr = X + (long)n * C;
            float xv[C];
#pragma unroll
            for (int q = 0; q < C / 4; q++) {
                float4 v = ((const float4*)xr)[q];
                xv[4 * q] = v.x; xv[4 * q + 1] = v.y;
                xv[4 * q + 2] = v.z; xv[4 * q + 3] = v.w;
            }
            for (int o = 0; o < nOut; o++) {
                float a = 0.0f;
#pragma unroll
                for (int c = 0; c < C; c++) a = fmaf(Ks[o * C + c], xv[c], a);
                out[(long)n * nOut + o] = a;
            }
        }
    }
}

extern "C" void kernel_launch(void* const* d_in, const int* in_sizes, int n_in,
                              void* d_out, int out_size) {
    const float* xn = (const float*)d_in[0];
    const int* Iv = (const int*)d_in[1];
    const int* Jv = (const int*)d_in[2];
    int idx = 3;
    if (n_in >= 7 && in_sizes[3] == 1) idx = 4;   // skip scalar n_nodes input
    const float* K1  = (const float*)d_in[idx];
    const float* KN2 = (const float*)d_in[idx + 1];
    const float* KNc = (const float*)d_in[idx + 2];
    int nE = in_sizes[1];
    int nN = in_sizes[0] / CIN;
    int nLayer = in_sizes[idx + 1] / (C * C);
    int nOut = in_sizes[idx + 2] / C;
    float* out = (float*)d_out;

    cudaFuncSetAttribute(k_layers, cudaFuncAttributeMaxDynamicSharedMemorySize,
                         SMEM_EDGE);

    int nPB = (nN + 63) / 64;
    int nZB = (nN + 255) / 256;
    k_pz<<<nPB + nZB, 256>>>(xn, K1, nN, nPB);
    k_degree<<<(nE + 255) / 256, 256>>>(Jv, nE);
    k_Wd<<<(nE + 255) / 256, 256>>>(Iv, Jv, nE);

    k_layers<<<NB, 256, SMEM_EDGE>>>(Iv, Jv, KN2, KNc, out,
                                     nE, nN, nLayer, nOut);
}

// round 17
// speedup vs baseline: 1.4450x; 1.0230x over previous
#include <cuda_runtime.h>
#include <cuda_bf16.h>
#include <cstdint>

#define CIN 128
#define C 64
#define H2f 0.01f
#define NNODES 50000
#define NEDGES 800000
#define GSB2 144          // smem row stride in bytes
#define WTILE 16          // edges per warp-iter
#define TILE_B (WTILE * GSB2)       // 2304 B per G tile
#define PSTRIDE (16 * GSB2)         // B nt-pair stride

// smem map: [0,36864) 8 warps x 2 G tiles; [36864,46080) Bs; then idx rings
#define OFF_BS   36864
#define OFF_SI   46080
#define OFF_SJ   48128
#define OFF_SW   50176
#define SMEM_EDGE 52224
#define NB 456            // 3 CTAs/SM x 152 — all resident (regs <= 84)

__device__ float g_deg[NNODES];
__device__ float g_W[NEDGES];
__device__ float g_buf[3][(long)NNODES * C];
__device__ uint32_t g_xbf[(long)NNODES * C / 2];   // bf16 mirror of x_cur
__device__ unsigned g_ctr = 0;
__device__ unsigned g_epoch = 0;

// ---------------- helpers ----------------
__device__ __forceinline__ uint32_t smem_u32(const void* p) {
    uint32_t a;
    asm("{ .reg .u64 t; cvta.to.shared.u64 t, %1; cvt.u32.u64 %0, t; }"
        : "=r"(a) : "l"(p));
    return a;
}
__device__ __forceinline__ float tanh_fast(float x) {
    float y;
    asm("tanh.approx.f32 %0, %1;" : "=f"(y) : "f"(x));
    return y;
}
__device__ __forceinline__ uint32_t bf16x2_pack(float a, float b) {
    uint32_t r;
    asm("cvt.rn.satfinite.bf16x2.f32 %0, %1, %2;" : "=r"(r) : "f"(b), "f"(a));
    return r;
}
__device__ __forceinline__ uint32_t gdiff(uint32_t xi, uint32_t xj, uint32_t w2) {
    __nv_bfloat162 a = *(__nv_bfloat162*)&xi;
    __nv_bfloat162 b = *(__nv_bfloat162*)&xj;
    __nv_bfloat162 w = *(__nv_bfloat162*)&w2;
    __nv_bfloat162 r = __hmul2(w, __hsub2(a, b));
    return *(uint32_t*)&r;
}
__device__ __forceinline__ float2 bf2f2(uint32_t u) {
    __nv_bfloat162 b = *(__nv_bfloat162*)&u;
    return __bfloat1622float2(b);
}
__device__ __forceinline__ void ldsm4(uint32_t (&r)[4], uint32_t addr) {
    asm volatile("ldmatrix.sync.aligned.m8n8.x4.shared.b16 {%0,%1,%2,%3}, [%4];"
        : "=r"(r[0]), "=r"(r[1]), "=r"(r[2]), "=r"(r[3]) : "r"(addr));
}
__device__ __forceinline__ void mma_bf16(float (&d)[4], const uint32_t (&a)[4],
                                         uint32_t b0, uint32_t b1) {
    asm volatile("mma.sync.aligned.m16n8k16.row.col.f32.bf16.bf16.f32 "
        "{%0,%1,%2,%3}, {%4,%5,%6,%7}, {%8,%9}, {%0,%1,%2,%3};"
        : "+f"(d[0]), "+f"(d[1]), "+f"(d[2]), "+f"(d[3])
        : "r"(a[0]), "r"(a[1]), "r"(a[2]), "r"(a[3]), "r"(b0), "r"(b1));
}
// grid-wide barrier (all NB blocks resident; sense-reversing epoch)
__device__ __forceinline__ void grid_sync() {
    __syncthreads();
    if (threadIdx.x == 0) {
        __threadfence();
        unsigned e = atomicAdd(&g_epoch, 0u);
        if (atomicAdd(&g_ctr, 1u) == (unsigned)(gridDim.x - 1)) {
            g_ctr = 0;
            __threadfence();
            atomicExch(&g_epoch, e + 1u);
        } else {
            while (atomicAdd(&g_epoch, 0u) == e) __nanosleep(64);
        }
        __threadfence();
    }
    __syncthreads();
}

// ---------------- setup kernels ----------------
__global__ void __launch_bounds__(256) k_pz(const float* __restrict__ xn,
                                            const float* __restrict__ K1,
                                            int nN, int nPB) {
    if (blockIdx.x >= nPB) {
        int i = (blockIdx.x - nPB) * 256 + threadIdx.x;
        if (i < nN) g_deg[i] = 0.0f;
        return;
    }
    __shared__ float Ks[C * CIN];
    __shared__ float xs[CIN * 64];
    int tid = threadIdx.x;
    for (int i = tid; i < C * CIN; i += 256) Ks[i] = K1[i];
    int n0 = blockIdx.x * 64;
    for (int i = tid; i < CIN * 64; i += 256) {
        int k = i >> 6, nl = i & 63;
        int n = n0 + nl;
        xs[i] = (n < nN) ? xn[(long)k * nN + n] : 0.0f;
    }
    __syncthreads();
    int nl = tid & 63;
    int cb = (tid >> 6) * 16;
    float acc[16];
#pragma unroll
    for (int j = 0; j < 16; j++) acc[j] = 0.0f;
    for (int k = 0; k < CIN; k++) {
        float xv = xs[k * 64 + nl];
#pragma unroll
        for (int j = 0; j < 16; j++) acc[j] = fmaf(Ks[(cb + j) * CIN + k], xv, acc[j]);
    }
    int n = n0 + nl;
    if (n < nN) {
#pragma unroll
        for (int j = 0; j < 16; j++) {
            float v = fmaxf(acc[j], 0.0f);
            g_buf[0][(long)n * C + cb + j] = v;
            g_buf[1][(long)n * C + cb + j] = v;
            g_buf[2][(long)n * C + cb + j] = v;
        }
#pragma unroll
        for (int j = 0; j < 8; j++) {
            float a = fmaxf(acc[2 * j], 0.0f), b = fmaxf(acc[2 * j + 1], 0.0f);
            g_xbf[(long)n * 32 + cb / 2 + j] = bf16x2_pack(a, b);
        }
    }
}

__global__ void k_degree(const int* __restrict__ Jv, int nE) {
    int e = blockIdx.x * blockDim.x + threadIdx.x;
    if (e < nE) atomicAdd(&g_deg[Jv[e]], 1.0f);
}

__global__ void k_Wd(const int* __restrict__ Iv, const int* __restrict__ Jv, int nE) {
    int e = blockIdx.x * blockDim.x + threadIdx.x;
    if (e < nE)
        g_W[e] = rsqrtf(g_deg[Iv[e]] + 1.0f) * rsqrtf(g_deg[Jv[e]] + 1.0f);
}

// ---------------- persistent multi-layer hot kernel ----------------
// Warp-autonomous 16-edge pipelines, no intra-loop barriers. 4-edge gather
// waves interleaved 1:1 with GEMM1 kt-steps (register-lean for 3 CTA/SM).
// T = tanh(D1) stays in registers (C-frag == A-frag identity) -> GEMM2.
// d staged bf16 in consumed G tile -> coalesced RED.v4. Layer boundary:
// grid_sync -> rotate + fused init -> grid_sync. Tail: fused k_out.
__global__ void __launch_bounds__(256, 3)
k_layers(const int* __restrict__ Iv, const int* __restrict__ Jv,
         const float* __restrict__ KN2, const float* __restrict__ KNc,
         float* __restrict__ out, int nE, int nN, int nLayer, int nOut)
{
    extern __shared__ __align__(16) char smem[];
    int tid = threadIdx.x, lane = tid & 31, wid = tid >> 5;
    int gid = lane >> 2, tig = lane & 3;
    int lh = lane & 15;

    char* Gw = smem + wid * (2 * TILE_B);              // 2 private G tiles
    __nv_bfloat16* Bs = (__nv_bfloat16*)(smem + OFF_BS);
    int*   sIw = (int*)(smem + OFF_SI) + wid * 64;     // [4][16]
    int*   sJw = (int*)(smem + OFF_SJ) + wid * 64;
    float* sWw = (float*)(smem + OFF_SW) + wid * 64;

    uint32_t gw0 = smem_u32(Gw);
    uint32_t bsb = smem_u32(Bs);
    int lrow = (lane & 7) + ((lane >> 3) & 1) * 8;
    int lcol = ((lane >> 4) & 1) * 8;
    int bg = lane >> 3;
    uint32_t bBase = bsb + (((bg >> 1) * 8) + (lane & 7)) * GSB2 + (bg & 1) * 16;

    const uint32_t* xb = g_xbf;
    long stride = (long)gridDim.x * 8 * WTILE;
    int n4 = nN * C / 4;
    int cur = 0, old = 1, nxt = 2;

    for (int l = 0; l < nLayer; l++) {
        const float* Km = KN2 + (long)l * C * C;
        float* A = g_buf[nxt];

        // ---- Bs[n][k] = Km[n*64+k] as bf16 (block-shared) ----
        for (int i = tid; i < C * 32; i += 256) {
            int n = i >> 5, kq = i & 31;
            *(uint32_t*)((char*)Bs + n * GSB2 + kq * 4) =
                bf16x2_pack(Km[n * 64 + 2 * kq], Km[n * 64 + 2 * kq + 1]);
        }
        __syncthreads();

        long e0 = ((long)blockIdx.x * 8 + wid) * WTILE;
        // warp-private idx loader: lanes 0-15 -> I,W ; 16-31 -> J
        auto load_idx = [&](long eb, int s) {
            long e = eb + lh;
            bool ok = e < (long)nE;
            if (lane < 16) {
                sIw[s * 16 + lh] = ok ? Iv[e] : 0;
                sWw[s * 16 + lh] = ok ? g_W[e] : 0.0f;
            } else {
                sJw[s * 16 + lh] = ok ? Jv[e] : 0;
            }
        };

        load_idx(e0, 0);
        load_idx(e0 + stride, 1);
        __syncwarp();
        // ---- prologue gather: tile 0 -> buf 0 ----
#pragma unroll 4
        for (int el = 0; el < WTILE; el++) {
            float w = sWw[el];
            uint32_t w2 = bf16x2_pack(w, w);
            uint32_t xi = xb[(long)sIw[el] * 32 + lane];
            uint32_t xj = xb[(long)sJw[el] * 32 + lane];
            *(uint32_t*)(Gw + el * GSB2 + lane * 4) = gdiff(xi, xj, w2);
        }

        int s0 = 0, curbuf = 0;
        for (; e0 < nE; e0 += stride) {
            __syncwarp();               // gather stores -> ldsm, idx visible
            uint32_t gcur_a = gw0 + curbuf * TILE_B;
            char* gcur = Gw + curbuf * TILE_B;
            char* gnext = Gw + (curbuf ^ 1) * TILE_B;
            load_idx(e0 + 2 * stride, (s0 + 2) & 3);

            int s1 = (s0 + 1) & 3;
            const int* sIc = sIw + s1 * 16;
            const int* sJc = sJw + s1 * 16;
            const float* sWc = sWw + s1 * 16;

            float acc[8][4];
#pragma unroll
            for (int nt = 0; nt < 8; nt++)
#pragma unroll
                for (int q = 0; q < 4; q++) acc[nt][q] = 0.0f;

            // ---- GEMM1 kt-steps interleaved with 4-edge gather waves ----
#pragma unroll
            for (int kt = 0; kt < 4; kt++) {
                // wave kt: load 4 edges of next tile
                uint32_t xiu[4], xju[4];
#pragma unroll
                for (int el = 0; el < 4; el++) {
                    int e = kt * 4 + el;
                    xiu[el] = xb[(long)sIc[e] * 32 + lane];
                    xju[el] = xb[(long)sJc[e] * 32 + lane];
                }
                // GEMM1 step kt (covers wave latency)
                uint32_t af[4];
                ldsm4(af, gcur_a + lrow * GSB2 + (kt * 16 + lcol) * 2);
#pragma unroll
                for (int p = 0; p < 4; p++) {
                    uint32_t bf[4];
                    ldsm4(bf, bBase + p * PSTRIDE + kt * 32);
                    mma_bf16(acc[2 * p], af, bf[0], bf[1]);
                    mma_bf16(acc[2 * p + 1], af, bf[2], bf[3]);
                }
                // store wave kt
#pragma unroll
                for (int el = 0; el < 4; el++) {
                    int e = kt * 4 + el;
                    float w = sWc[e];
                    uint32_t w2 = bf16x2_pack(w, w);
                    *(uint32_t*)(gnext + e * GSB2 + lane * 4) =
                        gdiff(xiu[el], xju[el], w2);
                }
            }
            // ---- tanh -> T in registers (C-frag -> A-frag identity) ----
            uint32_t t[4][4];
#pragma unroll
            for (int kt = 0; kt < 4; kt++) {
                t[kt][0] = bf16x2_pack(tanh_fast(acc[2 * kt][0]),
                                       tanh_fast(acc[2 * kt][1]));
                t[kt][1] = bf16x2_pack(tanh_fast(acc[2 * kt][2]),
                                       tanh_fast(acc[2 * kt][3]));
                t[kt][2] = bf16x2_pack(tanh_fast(acc[2 * kt + 1][0]),
                                       tanh_fast(acc[2 * kt + 1][1]));
                t[kt][3] = bf16x2_pack(tanh_fast(acc[2 * kt + 1][2]),
                                       tanh_fast(acc[2 * kt + 1][3]));
            }
            // ---- GEMM2: D2 = T * B (A from registers) ----
#pragma unroll
            for (int nt = 0; nt < 8; nt++)
#pragma unroll
                for (int q = 0; q < 4; q++) acc[nt][q] = 0.0f;
#pragma unroll
            for (int kt = 0; kt < 4; kt++) {
#pragma unroll
                for (int p = 0; p < 4; p++) {
                    uint32_t bf[4];
                    ldsm4(bf, bBase + p * PSTRIDE + kt * 32);
                    mma_bf16(acc[2 * p], t[kt], bf[0], bf[1]);
                    mma_bf16(acc[2 * p + 1], t[kt], bf[2], bf[3]);
                }
            }
            // ---- stage d (bf16) edge-major into consumed gcur ----
#pragma unroll
            for (int nt = 0; nt < 8; nt++) {
                int o = nt * 8 + tig * 2;
                *(uint32_t*)(gcur + gid * GSB2 + o * 2) =
                    bf16x2_pack(acc[nt][0], acc[nt][1]);
                *(uint32_t*)(gcur + (gid + 8) * GSB2 + o * 2) =
                    bf16x2_pack(acc[nt][2], acc[nt][3]);
            }
            __syncwarp();
            // ---- coalesced scatter: lanes 0-15 -> I (neg), 16-31 -> J ----
            {
                const int* sIs = sIw + s0 * 16;
                const int* sJs = sJw + s0 * 16;
                const float* sWs = sWw + s0 * 16;
#pragma unroll 4
                for (int el = 0; el < WTILE; el++) {
                    uint2 dpk = *(uint2*)(gcur + el * GSB2 + lh * 8);
                    float2 dlo = bf2f2(dpk.x);
                    float2 dhi = bf2f2(dpk.y);
                    float s = H2f * sWs[el];
                    if (lane < 16) s = -s;
                    long node = (lane < 16) ? sIs[el] : sJs[el];
                    float* p4 = A + node * 64 + 4 * lh;
                    asm volatile("red.global.add.v4.f32 [%0], {%1, %2, %3, %4};"
                                 :: "l"(p4), "f"(s * dlo.x), "f"(s * dlo.y),
                                    "f"(s * dhi.x), "f"(s * dhi.y) : "memory");
                }
            }
            s0 = s1;
            curbuf ^= 1;
        }

        // ---- layer boundary ----
        grid_sync();                    // all scatters of layer l complete
        int tsw = old; old = cur; cur = nxt; nxt = tsw;
        if (l + 1 < nLayer) {
            const float4* xc = (const float4*)g_buf[cur];
            const float4* xo = (const float4*)g_buf[old];
            float4* An = (float4*)g_buf[nxt];
            uint2* mir = (uint2*)g_xbf;
            for (int i = blockIdx.x * 256 + tid; i < n4; i += gridDim.x * 256) {
                float4 a = xc[i], b = xo[i];
                An[i] = make_float4(2.0f * a.x - b.x, 2.0f * a.y - b.y,
                                    2.0f * a.z - b.z, 2.0f * a.w - b.w);
                mir[i] = make_uint2(bf16x2_pack(a.x, a.y), bf16x2_pack(a.z, a.w));
            }
        }
        grid_sync();                    // init done before next layer
    }

    // ---- fused output: out[n][o] = sum_c KNc[o][c] * x[n][c] ----
    {
        float* Ks = (float*)smem;       // G region free after final grid_sync
        for (int i = tid; i < nOut * C; i += 256) Ks[i] = KNc[i];
        __syncthreads();
        const float* X = g_buf[cur];
        for (int n = blockIdx.x * 256 + tid; n < nN; n += gridDim.x * 256) {
            const float* xr = X + (long)n * C;
            float xv[C];
#pragma unroll
            for (int q = 0; q < C / 4; q++) {
                float4 v = ((const float4*)xr)[q];
                xv[4 * q] = v.x; xv[4 * q + 1] = v.y;
                xv[4 * q + 2] = v.z; xv[4 * q + 3] = v.w;
            }
            for (int o = 0; o < nOut; o++) {
                float a = 0.0f;
#pragma unroll
                for (int c = 0; c < C; c++) a = fmaf(Ks[o * C + c], xv[c], a);
                out[(long)n * nOut + o] = a;
            }
        }
    }
}

extern "C" void kernel_launch(void* const* d_in, const int* in_sizes, int n_in,
                              void* d_out, int out_size) {
    const float* xn = (const float*)d_in[0];
    const int* Iv = (const int*)d_in[1];
    const int* Jv = (const int*)d_in[2];
    int idx = 3;
    if (n_in >= 7 && in_sizes[3] == 1) idx = 4;   // skip scalar n_nodes input
    const float* K1  = (const float*)d_in[idx];
    const float* KN2 = (const float*)d_in[idx + 1];
    const float* KNc = (const float*)d_in[idx + 2];
    int nE = in_sizes[1];
    int nN = in_sizes[0] / CIN;
    int nLayer = in_sizes[idx + 1] / (C * C);
    int nOut = in_sizes[idx + 2] / C;
    float* out = (float*)d_out;

    cudaFuncSetAttribute(k_layers, cudaFuncAttributeMaxDynamicSharedMemorySize,
                         SMEM_EDGE);

    int nPB = (nN + 63) / 64;
    int nZB = (nN + 255) / 256;
    k_pz<<<nPB + nZB, 256>>>(xn, K1, nN, nPB);
    k_degree<<<(nE + 255) / 256, 256>>>(Jv, nE);
    k_Wd<<<(nE + 255) / 256, 256>>>(Iv, Jv, nE);

    k_layers<<<NB, 256, SMEM_EDGE>>>(Iv, Jv, KN2, KNc, out,
                                     nE, nN, nLayer, nOut);
}